// round 11
// baseline (speedup 1.0000x reference)
#include <cuda_runtime.h>
#include <cstdint>

#define NN 65536
#define DD 64
#define EE 1048576
#define SS 1024

typedef unsigned long long u64;

// Scratch (device globals — no allocation allowed)
__device__ float g_za[NN * DD];   // gather output (z), gemm1 input
__device__ float g_y[NN * DD];    // gemm1 output, gemm2 input
__device__ float g_z2[NN * DD];   // gemm2 output (pre-BN2); read by apply + next gather
// per-layer stats: layer l uses [l*256 .. l*256+256):
//   [+0:+64) sum1, [+64:+128) sumsq1   (gemm1 output stats)
//   [+128:+192) sum2, [+192:+256) sumsq2 (gemm2 output stats)
__device__ float g_stats[512];
__device__ int   g_deg[NN];
__device__ int   g_rowloc[NN];    // block-local exclusive prefix
__device__ int   g_fill[NN];
__device__ int   g_csr[EE];
__device__ int   g_boff[256];     // per-block CSR region base (atomic-allocated)
__device__ int   g_ctr[1];

// ---------------------------------------------------------------------------
// zero: out, g_deg, g_stats, g_ctr; 128 blocks x 256 threads
__global__ void init_kernel(float* __restrict__ out) {
    int i = blockIdx.x * 256 + threadIdx.x;              // 0 .. 32767
    ((float4*)out)[i] = make_float4(0.f, 0.f, 0.f, 0.f); // 32768 float4 = SS*128
    if (i < NN / 4) ((int4*)g_deg)[i] = make_int4(0, 0, 0, 0);
    if (i < 512) g_stats[i] = 0.f;
    if (i == 0) g_ctr[0] = 0;
}

__global__ void count_kernel(const int* __restrict__ ei) {
    int e = blockIdx.x * 256 + threadIdx.x;
    atomicAdd(&g_deg[__ldg(ei + EE + e)], 1);
}

// per-block (256 elems) exclusive scan; block CSR region base via atomicAdd
__global__ void scan_alloc_kernel() {
    __shared__ int wsum[8];
    int t = threadIdx.x;
    int i = blockIdx.x * 256 + t;
    int v = g_deg[i];
    int inc = v;
    #pragma unroll
    for (int o = 1; o < 32; o <<= 1) {
        int n = __shfl_up_sync(0xffffffffu, inc, o);
        if ((t & 31) >= o) inc += n;
    }
    if ((t & 31) == 31) wsum[t >> 5] = inc;
    __syncthreads();
    if (t < 8) {
        int w = wsum[t];
        #pragma unroll
        for (int o = 1; o < 8; o <<= 1) {
            int n = __shfl_up_sync(0xffu, w, o);
            if (t >= o) w += n;
        }
        wsum[t] = w;
    }
    __syncthreads();
    int warpoff = (t >= 32) ? wsum[(t >> 5) - 1] : 0;
    int loc = inc - v + warpoff;
    g_rowloc[i] = loc;
    g_fill[i]   = loc;
    if (t == 0) g_boff[blockIdx.x] = atomicAdd(&g_ctr[0], wsum[7]);
}

__global__ void fill_kernel(const int* __restrict__ ei) {
    int e = blockIdx.x * 256 + threadIdx.x;
    int s = __ldg(ei + e);
    int d = __ldg(ei + EE + e);
    int p = atomicAdd(&g_fill[d], 1) + g_boff[d >> 8];
    g_csr[p] = s;
}

// ---------------------------------------------------------------------------
// z[n] = (1+eps)*h[n] + sum over CSR neighbors -> g_za.
// LAYER==0: h = x (raw). LAYER==1: h = relu(bn2(g_z2)) applied on the fly
// (coeffs from layer-0 stats at g_stats[128..256)).
// 256 threads, 16 threads/node, 16 nodes/block.
template <int LAYER>
__global__ void __launch_bounds__(256)
gather_kernel(const float* __restrict__ x, const float* __restrict__ eps,
              const float* __restrict__ gamma, const float* __restrict__ beta) {
    const float4* src4 = LAYER ? (const float4*)g_z2 : (const float4*)x;
    int t = threadIdx.x;
    int n = blockIdx.x * 16 + (t >> 4);
    int q = t & 15;

    float4 sc, sh;
    if (LAYER == 1) {
        int c0 = q * 4;
        float scv[4], shv[4];
        #pragma unroll
        for (int j = 0; j < 4; j++) {
            float mu  = g_stats[128 + c0 + j] * (1.0f / NN);
            float var = g_stats[192 + c0 + j] * (1.0f / NN) - mu * mu;
            float s = __ldg(gamma + c0 + j) * rsqrtf(var + 1e-5f);
            scv[j] = s;
            shv[j] = __ldg(beta + c0 + j) - mu * s;
        }
        sc = make_float4(scv[0], scv[1], scv[2], scv[3]);
        sh = make_float4(shv[0], shv[1], shv[2], shv[3]);
    }

    int e0 = g_rowloc[n] + g_boff[n >> 8];
    int e1 = e0 + g_deg[n];
    float se = 1.0f + __ldg(eps + LAYER);

    float4 acc = __ldg(src4 + n * 16 + q);
    if (LAYER == 1) {
        acc.x = fmaxf(fmaf(acc.x, sc.x, sh.x), 0.f);
        acc.y = fmaxf(fmaf(acc.y, sc.y, sh.y), 0.f);
        acc.z = fmaxf(fmaf(acc.z, sc.z, sh.z), 0.f);
        acc.w = fmaxf(fmaf(acc.w, sc.w, sh.w), 0.f);
    }
    acc.x *= se; acc.y *= se; acc.z *= se; acc.w *= se;

    int e = e0;
    for (; e + 4 <= e1; e += 4) {
        int a0 = g_csr[e],     a1 = g_csr[e + 1];
        int a2 = g_csr[e + 2], a3 = g_csr[e + 3];
        float4 v0 = __ldg(src4 + a0 * 16 + q);
        float4 v1 = __ldg(src4 + a1 * 16 + q);
        float4 v2 = __ldg(src4 + a2 * 16 + q);
        float4 v3 = __ldg(src4 + a3 * 16 + q);
        if (LAYER == 1) {
            v0.x = fmaxf(fmaf(v0.x, sc.x, sh.x), 0.f);
            v0.y = fmaxf(fmaf(v0.y, sc.y, sh.y), 0.f);
            v0.z = fmaxf(fmaf(v0.z, sc.z, sh.z), 0.f);
            v0.w = fmaxf(fmaf(v0.w, sc.w, sh.w), 0.f);
            v1.x = fmaxf(fmaf(v1.x, sc.x, sh.x), 0.f);
            v1.y = fmaxf(fmaf(v1.y, sc.y, sh.y), 0.f);
            v1.z = fmaxf(fmaf(v1.z, sc.z, sh.z), 0.f);
            v1.w = fmaxf(fmaf(v1.w, sc.w, sh.w), 0.f);
            v2.x = fmaxf(fmaf(v2.x, sc.x, sh.x), 0.f);
            v2.y = fmaxf(fmaf(v2.y, sc.y, sh.y), 0.f);
            v2.z = fmaxf(fmaf(v2.z, sc.z, sh.z), 0.f);
            v2.w = fmaxf(fmaf(v2.w, sc.w, sh.w), 0.f);
            v3.x = fmaxf(fmaf(v3.x, sc.x, sh.x), 0.f);
            v3.y = fmaxf(fmaf(v3.y, sc.y, sh.y), 0.f);
            v3.z = fmaxf(fmaf(v3.z, sc.z, sh.z), 0.f);
            v3.w = fmaxf(fmaf(v3.w, sc.w, sh.w), 0.f);
        }
        acc.x += (v0.x + v1.x) + (v2.x + v3.x);
        acc.y += (v0.y + v1.y) + (v2.y + v3.y);
        acc.z += (v0.z + v1.z) + (v2.z + v3.z);
        acc.w += (v0.w + v1.w) + (v2.w + v3.w);
    }
    for (; e < e1; e++) {
        int a = g_csr[e];
        float4 v = __ldg(src4 + a * 16 + q);
        if (LAYER == 1) {
            v.x = fmaxf(fmaf(v.x, sc.x, sh.x), 0.f);
            v.y = fmaxf(fmaf(v.y, sc.y, sh.y), 0.f);
            v.z = fmaxf(fmaf(v.z, sc.z, sh.z), 0.f);
            v.w = fmaxf(fmaf(v.w, sc.w, sh.w), 0.f);
        }
        acc.x += v.x; acc.y += v.y; acc.z += v.z; acc.w += v.w;
    }
    ((float4*)g_za)[n * 16 + q] = acc;
}

// ---------------------------------------------------------------------------
// out = in @ W + b with f32x2 packed FMA mainloop + fused column stats.
// BN=false: g_za -> g_y, stats -> [layer*256 + 0/64)
// BN=true:  in := relu(bn1(g_y)) on load (coeffs from [layer*256+0/64)),
//           g_y -> g_z2, stats -> [layer*256 + 128/192)
template <bool BN>
__global__ void __launch_bounds__(128)
gemm_kernel(const float* __restrict__ W, const float* __restrict__ bias,
            const float* __restrict__ gamma, const float* __restrict__ beta,
            int layer) {
    const float* in = BN ? g_y : g_za;
    float* out      = BN ? g_z2 : g_y;
    __shared__ float4 zs4[128 * 16];  // 32 KB, [row][c4 ^ (row>>3)]
    __shared__ float4 ws4[64 * 16];   // 16 KB
    int t = threadIdx.x;

    #pragma unroll
    for (int p = 0; p < 8; p++)
        ws4[t + p * 128] = __ldg(((const float4*)W) + t + p * 128);

    int c4 = t & 15;
    float4 sc, sh;
    if (BN) {
        int c0 = c4 * 4;
        float scv[4], shv[4];
        #pragma unroll
        for (int j = 0; j < 4; j++) {
            float mu  = g_stats[layer * 256 + c0 + j]      * (1.0f / NN);
            float var = g_stats[layer * 256 + 64 + c0 + j] * (1.0f / NN) - mu * mu;
            float s = __ldg(gamma + c0 + j) * rsqrtf(var + 1e-5f);
            scv[j] = s;
            shv[j] = __ldg(beta + c0 + j) - mu * s;
        }
        sc = make_float4(scv[0], scv[1], scv[2], scv[3]);
        sh = make_float4(shv[0], shv[1], shv[2], shv[3]);
    }
    const float4* in4 = (const float4*)(in + (size_t)blockIdx.x * 128 * DD);
    #pragma unroll
    for (int p = 0; p < 16; p++) {
        int row = (t >> 4) + p * 8;
        float4 v = __ldg(in4 + row * 16 + c4);
        if (BN) {
            v.x = fmaxf(fmaf(v.x, sc.x, sh.x), 0.f);
            v.y = fmaxf(fmaf(v.y, sc.y, sh.y), 0.f);
            v.z = fmaxf(fmaf(v.z, sc.z, sh.z), 0.f);
            v.w = fmaxf(fmaf(v.w, sc.w, sh.w), 0.f);
        }
        zs4[row * 16 + (c4 ^ p)] = v;   // row>>3 == p
    }
    __syncthreads();

    int tr = t >> 3, tc = t & 7;
    int rbase = tr * 8;
    u64 acc2[8][4];
    #pragma unroll
    for (int i = 0; i < 8; i++)
        #pragma unroll
        for (int j = 0; j < 4; j++) acc2[i][j] = 0ull;

    #pragma unroll
    for (int kc = 0; kc < 16; kc++) {
        u64 b2[4][4];
        #pragma unroll
        for (int kk = 0; kk < 4; kk++) {
            const ulonglong2* wp = (const ulonglong2*)(ws4 + (kc * 4 + kk) * 16 + tc * 2);
            ulonglong2 p0 = wp[0];
            ulonglong2 p1 = wp[1];
            b2[kk][0] = p0.x; b2[kk][1] = p0.y;
            b2[kk][2] = p1.x; b2[kk][3] = p1.y;
        }
        #pragma unroll
        for (int ri = 0; ri < 8; ri++) {
            float4 a = zs4[(rbase + ri) * 16 + (kc ^ tr)];  // row>>3 == tr
            u64 d0, d1, d2, d3;
            asm("mov.b64 %0, {%1, %1};" : "=l"(d0) : "r"(__float_as_uint(a.x)));
            asm("mov.b64 %0, {%1, %1};" : "=l"(d1) : "r"(__float_as_uint(a.y)));
            asm("mov.b64 %0, {%1, %1};" : "=l"(d2) : "r"(__float_as_uint(a.z)));
            asm("mov.b64 %0, {%1, %1};" : "=l"(d3) : "r"(__float_as_uint(a.w)));
            #pragma unroll
            for (int j = 0; j < 4; j++) {
                asm("fma.rn.f32x2 %0, %1, %2, %0;" : "+l"(acc2[ri][j]) : "l"(d0), "l"(b2[0][j]));
                asm("fma.rn.f32x2 %0, %1, %2, %0;" : "+l"(acc2[ri][j]) : "l"(d1), "l"(b2[1][j]));
                asm("fma.rn.f32x2 %0, %1, %2, %0;" : "+l"(acc2[ri][j]) : "l"(d2), "l"(b2[2][j]));
                asm("fma.rn.f32x2 %0, %1, %2, %0;" : "+l"(acc2[ri][j]) : "l"(d3), "l"(b2[3][j]));
            }
        }
    }

    float4 bb0 = __ldg(((const float4*)bias) + tc * 2);
    float4 bb1 = __ldg(((const float4*)bias) + tc * 2 + 1);
    float bbv[8] = {bb0.x, bb0.y, bb0.z, bb0.w, bb1.x, bb1.y, bb1.z, bb1.w};
    float cs[8], cq[8];
    #pragma unroll
    for (int j = 0; j < 8; j++) { cs[j] = 0.f; cq[j] = 0.f; }
    #pragma unroll
    for (int ri = 0; ri < 8; ri++) {
        int row = rbase + ri;
        float o[8];
        #pragma unroll
        for (int j = 0; j < 4; j++) {
            unsigned lo, hi;
            asm("mov.b64 {%0, %1}, %2;" : "=r"(lo), "=r"(hi) : "l"(acc2[ri][j]));
            o[2 * j]     = __uint_as_float(lo) + bbv[2 * j];
            o[2 * j + 1] = __uint_as_float(hi) + bbv[2 * j + 1];
        }
        float* op = out + ((size_t)blockIdx.x * 128 + row) * DD + tc * 8;
        *(float4*)op       = make_float4(o[0], o[1], o[2], o[3]);
        *(float4*)(op + 4) = make_float4(o[4], o[5], o[6], o[7]);
        #pragma unroll
        for (int j = 0; j < 8; j++) {
            cs[j] += o[j];
            cq[j] += o[j] * o[j];
        }
    }

    __syncthreads();  // reuse zs4 as reduction buffer
    float* red = (float*)zs4;
    #pragma unroll
    for (int j = 0; j < 8; j++) {
        red[tr * 64 + tc * 8 + j]        = cs[j];
        red[1024 + tr * 64 + tc * 8 + j] = cq[j];
    }
    __syncthreads();
    if (t < 64) {
        float s1 = 0.f, s2 = 0.f;
        #pragma unroll
        for (int g = 0; g < 16; g++) {
            s1 += red[g * 64 + t];
            s2 += red[1024 + g * 64 + t];
        }
        int off = layer * 256 + (BN ? 128 : 0);
        atomicAdd(&g_stats[off + t], s1);
        atomicAdd(&g_stats[off + 64 + t], s2);
    }
}

// ---------------------------------------------------------------------------
// segmax of relu(bn2(g_z2)) into out[:, layer*64 : layer*64+64]  (no h store)
__global__ void __launch_bounds__(256)
apply_kernel(const int* __restrict__ n2s, float* __restrict__ out,
             const float* __restrict__ gamma, const float* __restrict__ beta,
             int layer) {
    __shared__ float red[16 * DD];
    __shared__ float ssc[64], ssh[64];
    int t = threadIdx.x, b = blockIdx.x;
    if (t < 64) {
        float mu  = g_stats[layer * 256 + 128 + t] * (1.0f / NN);
        float var = g_stats[layer * 256 + 192 + t] * (1.0f / NN) - mu * mu;
        float s = __ldg(gamma + t) * rsqrtf(var + 1e-5f);
        ssc[t] = s;
        ssh[t] = __ldg(beta + t) - mu * s;
    }
    __syncthreads();

    int g = t >> 4, q = t & 15;
    int c0 = q * 4;
    float s0 = ssc[c0], s1 = ssc[c0 + 1], s2 = ssc[c0 + 2], s3 = ssc[c0 + 3];
    float h0 = ssh[c0], h1 = ssh[c0 + 1], h2 = ssh[c0 + 2], h3 = ssh[c0 + 3];

    float4 m = make_float4(0.f, 0.f, 0.f, 0.f);
    #pragma unroll
    for (int p = 0; p < 4; p++) {
        int row = b * 64 + p * 16 + g;
        float4 v = *(const float4*)(g_z2 + (size_t)row * DD + c0);
        v.x = fmaxf(fmaf(v.x, s0, h0), 0.f);
        v.y = fmaxf(fmaf(v.y, s1, h1), 0.f);
        v.z = fmaxf(fmaf(v.z, s2, h2), 0.f);
        v.w = fmaxf(fmaf(v.w, s3, h3), 0.f);
        m.x = fmaxf(m.x, v.x); m.y = fmaxf(m.y, v.y);
        m.z = fmaxf(m.z, v.z); m.w = fmaxf(m.w, v.w);
    }
    red[g * DD + c0 + 0] = m.x; red[g * DD + c0 + 1] = m.y;
    red[g * DD + c0 + 2] = m.z; red[g * DD + c0 + 3] = m.w;
    __syncthreads();

    if (t < DD) {
        float mv = red[t];
        #pragma unroll
        for (int gg = 1; gg < 16; gg++) mv = fmaxf(mv, red[gg * DD + t]);
        int sA = __ldg(n2s + b * 64), sB = __ldg(n2s + b * 64 + 63);
        if (sA == sB) {
            unsigned* p = (unsigned*)(out + (size_t)sA * 128 + layer * 64 + t);
            asm volatile("red.global.max.u32 [%0], %1;"
                         :: "l"(p), "r"(__float_as_uint(mv)) : "memory");
        } else {
            // correctness fallback: per-row segment max
            for (int r = 0; r < 64; r++) {
                int seg = __ldg(n2s + b * 64 + r);
                float zv = g_z2[((size_t)b * 64 + r) * DD + t];
                float v = fmaxf(fmaf(zv, ssc[t], ssh[t]), 0.f);
                unsigned* p = (unsigned*)(out + (size_t)seg * 128 + layer * 64 + t);
                asm volatile("red.global.max.u32 [%0], %1;"
                             :: "l"(p), "r"(__float_as_uint(v)) : "memory");
            }
        }
    }
}

// ---------------------------------------------------------------------------
extern "C" void kernel_launch(void* const* d_in, const int* in_sizes, int n_in,
                              void* d_out, int out_size) {
    const float* x   = (const float*)d_in[0];
    const int*   ei  = (const int*)d_in[1];
    const int*   n2s = (const int*)d_in[2];
    const float* eps = (const float*)d_in[3];
    const float* W1  = (const float*)d_in[4];
    const float* b1  = (const float*)d_in[5];
    const float* gm  = (const float*)d_in[6];
    const float* bm  = (const float*)d_in[7];
    const float* W2  = (const float*)d_in[8];
    const float* b2  = (const float*)d_in[9];
    const float* go  = (const float*)d_in[10];
    const float* bo  = (const float*)d_in[11];
    float* out = (float*)d_out;

    init_kernel<<<128, 256>>>(out);
    count_kernel<<<EE / 256, 256>>>(ei);
    scan_alloc_kernel<<<NN / 256, 256>>>();
    fill_kernel<<<EE / 256, 256>>>(ei);

    // layer 0
    gather_kernel<0><<<NN / 16, 256>>>(x, eps, nullptr, nullptr);
    gemm_kernel<false><<<NN / 128, 128>>>(W1, b1, nullptr, nullptr, 0);
    gemm_kernel<true><<<NN / 128, 128>>>(W2, b2, gm, bm, 0);
    apply_kernel<<<NN / 64, 256>>>(n2s, out, go, bo, 0);

    // layer 1 (gather applies layer-0 BN2+ReLU on the fly)
    gather_kernel<1><<<NN / 16, 256>>>(x, eps, go, bo);
    gemm_kernel<false><<<NN / 128, 128>>>(W1 + DD * DD, b1 + DD, nullptr, nullptr, 1);
    gemm_kernel<true><<<NN / 128, 128>>>(W2 + DD * DD, b2 + DD, gm + DD, bm + DD, 1);
    apply_kernel<<<NN / 64, 256>>>(n2s, out, go + DD, bo + DD, 1);
}

// round 12
// speedup vs baseline: 1.0126x; 1.0126x over previous
#include <cuda_runtime.h>
#include <cstdint>

#define NN 65536
#define DD 64
#define EE 1048576
#define SS 1024

typedef unsigned long long u64;

// Scratch (device globals — no allocation allowed)
__device__ float g_za[NN * DD];   // gather output (z), gemm1 input
__device__ float g_y[NN * DD];    // gemm1 output, gemm2 input
__device__ float g_z2[NN * DD];   // gemm2 output (pre-BN2)
__device__ float g_h[NN * DD];    // layer-0 output h (input to layer-1 gather)
// per-layer stats: layer l uses [l*256 .. l*256+256):
//   [+0:+64) sum1, [+64:+128) sumsq1   (gemm1 output stats)
//   [+128:+192) sum2, [+192:+256) sumsq2 (gemm2 output stats)
__device__ float g_stats[512];
__device__ int   g_deg[NN];
__device__ int   g_rowloc[NN];    // block-local exclusive prefix
__device__ int   g_slot[EE];      // within-node slot per edge (from count)
__device__ int   g_csr[EE];
__device__ int   g_boff[256];     // per-block CSR region base (atomic-allocated)
__device__ int   g_ctr[1];

// ---------------------------------------------------------------------------
// zero: out, g_deg, g_stats, g_ctr; 128 blocks x 256 threads
__global__ void init_kernel(float* __restrict__ out) {
    int i = blockIdx.x * 256 + threadIdx.x;              // 0 .. 32767
    ((float4*)out)[i] = make_float4(0.f, 0.f, 0.f, 0.f); // 32768 float4 = SS*128
    if (i < NN / 4) ((int4*)g_deg)[i] = make_int4(0, 0, 0, 0);
    if (i < 512) g_stats[i] = 0.f;
    if (i == 0) g_ctr[0] = 0;
}

// count degrees AND record each edge's within-node slot (coalesced store)
__global__ void count_slot_kernel(const int* __restrict__ ei) {
    int e = blockIdx.x * 256 + threadIdx.x;
    g_slot[e] = atomicAdd(&g_deg[__ldg(ei + EE + e)], 1);
}

// per-block (256 elems) exclusive scan; block CSR region base via atomicAdd
__global__ void scan_alloc_kernel() {
    __shared__ int wsum[8];
    int t = threadIdx.x;
    int i = blockIdx.x * 256 + t;
    int v = g_deg[i];
    int inc = v;
    #pragma unroll
    for (int o = 1; o < 32; o <<= 1) {
        int n = __shfl_up_sync(0xffffffffu, inc, o);
        if ((t & 31) >= o) inc += n;
    }
    if ((t & 31) == 31) wsum[t >> 5] = inc;
    __syncthreads();
    if (t < 8) {
        int w = wsum[t];
        #pragma unroll
        for (int o = 1; o < 8; o <<= 1) {
            int n = __shfl_up_sync(0xffu, w, o);
            if (t >= o) w += n;
        }
        wsum[t] = w;
    }
    __syncthreads();
    int warpoff = (t >= 32) ? wsum[(t >> 5) - 1] : 0;
    g_rowloc[i] = inc - v + warpoff;
    if (t == 0) g_boff[blockIdx.x] = atomicAdd(&g_ctr[0], wsum[7]);
}

// atomic-free CSR fill using precomputed slots
__global__ void fill_kernel(const int* __restrict__ ei) {
    int e = blockIdx.x * 256 + threadIdx.x;
    int s = __ldg(ei + e);
    int d = __ldg(ei + EE + e);
    int p = g_rowloc[d] + g_boff[d >> 8] + g_slot[e];
    g_csr[p] = s;
}

// ---------------------------------------------------------------------------
// z[n] = (1+eps)*h[n] + sum over CSR neighbors -> g_za.
// 256 threads, 16 threads/node, 16 nodes/block (high-occupancy, latency-bound).
__global__ void __launch_bounds__(256)
gather_kernel(const float* __restrict__ x, const float* __restrict__ eps, int layer) {
    const float4* h4 = layer ? (const float4*)g_h : (const float4*)x;
    int t = threadIdx.x;
    int n = blockIdx.x * 16 + (t >> 4);
    int q = t & 15;
    int e0 = g_rowloc[n] + g_boff[n >> 8];
    int e1 = e0 + g_deg[n];
    float se = 1.0f + __ldg(eps + layer);
    float4 acc = __ldg(h4 + n * 16 + q);
    acc.x *= se; acc.y *= se; acc.z *= se; acc.w *= se;
    int e = e0;
    for (; e + 4 <= e1; e += 4) {
        int a0 = g_csr[e],     a1 = g_csr[e + 1];
        int a2 = g_csr[e + 2], a3 = g_csr[e + 3];
        float4 v0 = __ldg(h4 + a0 * 16 + q);
        float4 v1 = __ldg(h4 + a1 * 16 + q);
        float4 v2 = __ldg(h4 + a2 * 16 + q);
        float4 v3 = __ldg(h4 + a3 * 16 + q);
        acc.x += (v0.x + v1.x) + (v2.x + v3.x);
        acc.y += (v0.y + v1.y) + (v2.y + v3.y);
        acc.z += (v0.z + v1.z) + (v2.z + v3.z);
        acc.w += (v0.w + v1.w) + (v2.w + v3.w);
    }
    for (; e < e1; e++) {
        int a = g_csr[e];
        float4 v = __ldg(h4 + a * 16 + q);
        acc.x += v.x; acc.y += v.y; acc.z += v.z; acc.w += v.w;
    }
    ((float4*)g_za)[n * 16 + q] = acc;
}

// ---------------------------------------------------------------------------
// out = in @ W + b with f32x2 packed FMA mainloop + fused column stats.
// BN=false: g_za -> g_y, stats -> [layer*256 + 0/64)
// BN=true:  in := relu(bn1(g_y)) on load (coeffs from [layer*256+0/64)),
//           g_y -> g_z2, stats -> [layer*256 + 128/192)
template <bool BN>
__global__ void __launch_bounds__(128)
gemm_kernel(const float* __restrict__ W, const float* __restrict__ bias,
            const float* __restrict__ gamma, const float* __restrict__ beta,
            int layer) {
    const float* in = BN ? g_y : g_za;
    float* out      = BN ? g_z2 : g_y;
    __shared__ float4 zs4[128 * 16];  // 32 KB, [row][c4 ^ (row>>3)]
    __shared__ float4 ws4[64 * 16];   // 16 KB
    int t = threadIdx.x;

    #pragma unroll
    for (int p = 0; p < 8; p++)
        ws4[t + p * 128] = __ldg(((const float4*)W) + t + p * 128);

    int c4 = t & 15;
    float4 sc, sh;
    if (BN) {
        int c0 = c4 * 4;
        float scv[4], shv[4];
        #pragma unroll
        for (int j = 0; j < 4; j++) {
            float mu  = g_stats[layer * 256 + c0 + j]      * (1.0f / NN);
            float var = g_stats[layer * 256 + 64 + c0 + j] * (1.0f / NN) - mu * mu;
            float s = __ldg(gamma + c0 + j) * rsqrtf(var + 1e-5f);
            scv[j] = s;
            shv[j] = __ldg(beta + c0 + j) - mu * s;
        }
        sc = make_float4(scv[0], scv[1], scv[2], scv[3]);
        sh = make_float4(shv[0], shv[1], shv[2], shv[3]);
    }
    const float4* in4 = (const float4*)(in + (size_t)blockIdx.x * 128 * DD);
    #pragma unroll
    for (int p = 0; p < 16; p++) {
        int row = (t >> 4) + p * 8;
        float4 v = __ldg(in4 + row * 16 + c4);
        if (BN) {
            v.x = fmaxf(fmaf(v.x, sc.x, sh.x), 0.f);
            v.y = fmaxf(fmaf(v.y, sc.y, sh.y), 0.f);
            v.z = fmaxf(fmaf(v.z, sc.z, sh.z), 0.f);
            v.w = fmaxf(fmaf(v.w, sc.w, sh.w), 0.f);
        }
        zs4[row * 16 + (c4 ^ p)] = v;   // row>>3 == p
    }
    __syncthreads();

    int tr = t >> 3, tc = t & 7;
    int rbase = tr * 8;
    u64 acc2[8][4];
    #pragma unroll
    for (int i = 0; i < 8; i++)
        #pragma unroll
        for (int j = 0; j < 4; j++) acc2[i][j] = 0ull;

    #pragma unroll
    for (int kc = 0; kc < 16; kc++) {
        u64 b2[4][4];
        #pragma unroll
        for (int kk = 0; kk < 4; kk++) {
            const ulonglong2* wp = (const ulonglong2*)(ws4 + (kc * 4 + kk) * 16 + tc * 2);
            ulonglong2 p0 = wp[0];
            ulonglong2 p1 = wp[1];
            b2[kk][0] = p0.x; b2[kk][1] = p0.y;
            b2[kk][2] = p1.x; b2[kk][3] = p1.y;
        }
        #pragma unroll
        for (int ri = 0; ri < 8; ri++) {
            float4 a = zs4[(rbase + ri) * 16 + (kc ^ tr)];  // row>>3 == tr
            u64 d0, d1, d2, d3;
            asm("mov.b64 %0, {%1, %1};" : "=l"(d0) : "r"(__float_as_uint(a.x)));
            asm("mov.b64 %0, {%1, %1};" : "=l"(d1) : "r"(__float_as_uint(a.y)));
            asm("mov.b64 %0, {%1, %1};" : "=l"(d2) : "r"(__float_as_uint(a.z)));
            asm("mov.b64 %0, {%1, %1};" : "=l"(d3) : "r"(__float_as_uint(a.w)));
            #pragma unroll
            for (int j = 0; j < 4; j++) {
                asm("fma.rn.f32x2 %0, %1, %2, %0;" : "+l"(acc2[ri][j]) : "l"(d0), "l"(b2[0][j]));
                asm("fma.rn.f32x2 %0, %1, %2, %0;" : "+l"(acc2[ri][j]) : "l"(d1), "l"(b2[1][j]));
                asm("fma.rn.f32x2 %0, %1, %2, %0;" : "+l"(acc2[ri][j]) : "l"(d2), "l"(b2[2][j]));
                asm("fma.rn.f32x2 %0, %1, %2, %0;" : "+l"(acc2[ri][j]) : "l"(d3), "l"(b2[3][j]));
            }
        }
    }

    float4 bb0 = __ldg(((const float4*)bias) + tc * 2);
    float4 bb1 = __ldg(((const float4*)bias) + tc * 2 + 1);
    float bbv[8] = {bb0.x, bb0.y, bb0.z, bb0.w, bb1.x, bb1.y, bb1.z, bb1.w};
    float cs[8], cq[8];
    #pragma unroll
    for (int j = 0; j < 8; j++) { cs[j] = 0.f; cq[j] = 0.f; }
    #pragma unroll
    for (int ri = 0; ri < 8; ri++) {
        int row = rbase + ri;
        float o[8];
        #pragma unroll
        for (int j = 0; j < 4; j++) {
            unsigned lo, hi;
            asm("mov.b64 {%0, %1}, %2;" : "=r"(lo), "=r"(hi) : "l"(acc2[ri][j]));
            o[2 * j]     = __uint_as_float(lo) + bbv[2 * j];
            o[2 * j + 1] = __uint_as_float(hi) + bbv[2 * j + 1];
        }
        float* op = out + ((size_t)blockIdx.x * 128 + row) * DD + tc * 8;
        *(float4*)op       = make_float4(o[0], o[1], o[2], o[3]);
        *(float4*)(op + 4) = make_float4(o[4], o[5], o[6], o[7]);
        #pragma unroll
        for (int j = 0; j < 8; j++) {
            cs[j] += o[j];
            cq[j] += o[j] * o[j];
        }
    }

    __syncthreads();  // reuse zs4 as reduction buffer
    float* red = (float*)zs4;
    #pragma unroll
    for (int j = 0; j < 8; j++) {
        red[tr * 64 + tc * 8 + j]        = cs[j];
        red[1024 + tr * 64 + tc * 8 + j] = cq[j];
    }
    __syncthreads();
    if (t < 64) {
        float s1 = 0.f, s2 = 0.f;
        #pragma unroll
        for (int g = 0; g < 16; g++) {
            s1 += red[g * 64 + t];
            s2 += red[1024 + g * 64 + t];
        }
        int off = layer * 256 + (BN ? 128 : 0);
        atomicAdd(&g_stats[off + t], s1);
        atomicAdd(&g_stats[off + 64 + t], s2);
    }
}

// ---------------------------------------------------------------------------
// h = relu(bn2(g_z2)); segment-max into out[:, layer*64 : layer*64+64].
// LAST: skip the g_h store on the final layer (h unused afterwards).
template <bool LAST>
__global__ void __launch_bounds__(256)
apply_kernel(const int* __restrict__ n2s, float* __restrict__ out,
             const float* __restrict__ gamma, const float* __restrict__ beta,
             int layer) {
    __shared__ float red[16 * DD];
    __shared__ float ssc[64], ssh[64];
    int t = threadIdx.x, b = blockIdx.x;
    if (t < 64) {
        float mu  = g_stats[layer * 256 + 128 + t] * (1.0f / NN);
        float var = g_stats[layer * 256 + 192 + t] * (1.0f / NN) - mu * mu;
        float s = __ldg(gamma + t) * rsqrtf(var + 1e-5f);
        ssc[t] = s;
        ssh[t] = __ldg(beta + t) - mu * s;
    }
    __syncthreads();

    int g = t >> 4, q = t & 15;
    int c0 = q * 4;
    float s0 = ssc[c0], s1 = ssc[c0 + 1], s2 = ssc[c0 + 2], s3 = ssc[c0 + 3];
    float h0 = ssh[c0], h1 = ssh[c0 + 1], h2 = ssh[c0 + 2], h3 = ssh[c0 + 3];

    float4 m = make_float4(0.f, 0.f, 0.f, 0.f);
    #pragma unroll
    for (int p = 0; p < 4; p++) {
        int row = b * 64 + p * 16 + g;
        float4 v = *(const float4*)(g_z2 + (size_t)row * DD + c0);
        v.x = fmaxf(fmaf(v.x, s0, h0), 0.f);
        v.y = fmaxf(fmaf(v.y, s1, h1), 0.f);
        v.z = fmaxf(fmaf(v.z, s2, h2), 0.f);
        v.w = fmaxf(fmaf(v.w, s3, h3), 0.f);
        if (!LAST) *(float4*)(g_h + (size_t)row * DD + c0) = v;
        m.x = fmaxf(m.x, v.x); m.y = fmaxf(m.y, v.y);
        m.z = fmaxf(m.z, v.z); m.w = fmaxf(m.w, v.w);
    }
    red[g * DD + c0 + 0] = m.x; red[g * DD + c0 + 1] = m.y;
    red[g * DD + c0 + 2] = m.z; red[g * DD + c0 + 3] = m.w;
    __syncthreads();

    if (t < DD) {
        float mv = red[t];
        #pragma unroll
        for (int gg = 1; gg < 16; gg++) mv = fmaxf(mv, red[gg * DD + t]);
        int sA = __ldg(n2s + b * 64), sB = __ldg(n2s + b * 64 + 63);
        if (sA == sB) {
            unsigned* p = (unsigned*)(out + (size_t)sA * 128 + layer * 64 + t);
            asm volatile("red.global.max.u32 [%0], %1;"
                         :: "l"(p), "r"(__float_as_uint(mv)) : "memory");
        } else {
            // correctness fallback: per-row segment max (recompute bn on the fly)
            for (int r = 0; r < 64; r++) {
                int seg = __ldg(n2s + b * 64 + r);
                float zv = g_z2[((size_t)b * 64 + r) * DD + t];
                float v = fmaxf(fmaf(zv, ssc[t], ssh[t]), 0.f);
                unsigned* p = (unsigned*)(out + (size_t)seg * 128 + layer * 64 + t);
                asm volatile("red.global.max.u32 [%0], %1;"
                             :: "l"(p), "r"(__float_as_uint(v)) : "memory");
            }
        }
    }
}

// ---------------------------------------------------------------------------
extern "C" void kernel_launch(void* const* d_in, const int* in_sizes, int n_in,
                              void* d_out, int out_size) {
    const float* x   = (const float*)d_in[0];
    const int*   ei  = (const int*)d_in[1];
    const int*   n2s = (const int*)d_in[2];
    const float* eps = (const float*)d_in[3];
    const float* W1  = (const float*)d_in[4];
    const float* b1  = (const float*)d_in[5];
    const float* gm  = (const float*)d_in[6];
    const float* bm  = (const float*)d_in[7];
    const float* W2  = (const float*)d_in[8];
    const float* b2  = (const float*)d_in[9];
    const float* go  = (const float*)d_in[10];
    const float* bo  = (const float*)d_in[11];
    float* out = (float*)d_out;

    init_kernel<<<128, 256>>>(out);
    count_slot_kernel<<<EE / 256, 256>>>(ei);
    scan_alloc_kernel<<<NN / 256, 256>>>();
    fill_kernel<<<EE / 256, 256>>>(ei);

    for (int l = 0; l < 2; l++) {
        gather_kernel<<<NN / 16, 256>>>(x, eps, l);
        gemm_kernel<false><<<NN / 128, 128>>>(W1 + l * DD * DD, b1 + l * DD,
                                              nullptr, nullptr, l);
        gemm_kernel<true><<<NN / 128, 128>>>(W2 + l * DD * DD, b2 + l * DD,
                                             gm + l * DD, bm + l * DD, l);
        if (l == 0)
            apply_kernel<false><<<NN / 64, 256>>>(n2s, out, go, bo, 0);
        else
            apply_kernel<true><<<NN / 64, 256>>>(n2s, out, go + DD, bo + DD, 1);
    }
}

// round 13
// speedup vs baseline: 1.0533x; 1.0402x over previous
#include <cuda_runtime.h>
#include <cuda_fp16.h>
#include <cstdint>

#define NN 65536
#define DD 64
#define EE 1048576
#define SS 1024

typedef unsigned long long u64;

// Scratch (device globals — no allocation allowed)
__device__ __half g_xh[NN * DD];  // fp16 gather source: x (layer 0) then h (layer 1)
__device__ float g_za[NN * DD];   // gather output (z), gemm1 input
__device__ float g_y[NN * DD];    // gemm1 output, gemm2 input
__device__ float g_z2[NN * DD];   // gemm2 output (pre-BN2)
// per-layer stats: layer l uses [l*256 .. l*256+256):
//   [+0:+64) sum1, [+64:+128) sumsq1   (gemm1 output stats)
//   [+128:+192) sum2, [+192:+256) sumsq2 (gemm2 output stats)
__device__ float g_stats[512];
__device__ int   g_deg[NN];
__device__ int   g_rowloc[NN];    // block-local exclusive prefix
__device__ int   g_slot[EE];      // within-node slot per edge (from count)
__device__ int   g_csr[EE];
__device__ int   g_boff[256];     // per-block CSR region base (atomic-allocated)
__device__ int   g_ctr[1];

// ---------------------------------------------------------------------------
// grid 4096 x 256: convert x -> fp16 cache; zero out/deg/stats/ctr
__global__ void init_kernel(float* __restrict__ out, const float* __restrict__ x) {
    int i = blockIdx.x * 256 + threadIdx.x;              // 0 .. 1048575 (uint2 idx)
    float4 v = __ldg(((const float4*)x) + i);
    uint2 r;
    *(__half2*)&r.x = __floats2half2_rn(v.x, v.y);
    *(__half2*)&r.y = __floats2half2_rn(v.z, v.w);
    ((uint2*)g_xh)[i] = r;
    if (i < SS * 128 / 4) ((float4*)out)[i] = make_float4(0.f, 0.f, 0.f, 0.f);
    if (i < NN / 4) ((int4*)g_deg)[i] = make_int4(0, 0, 0, 0);
    if (i < 512) g_stats[i] = 0.f;
    if (i == 0) g_ctr[0] = 0;
}

// count degrees AND record each edge's within-node slot (coalesced store)
__global__ void count_slot_kernel(const int* __restrict__ ei) {
    int e = blockIdx.x * 256 + threadIdx.x;
    g_slot[e] = atomicAdd(&g_deg[__ldg(ei + EE + e)], 1);
}

// per-block (256 elems) exclusive scan; block CSR region base via atomicAdd
__global__ void scan_alloc_kernel() {
    __shared__ int wsum[8];
    int t = threadIdx.x;
    int i = blockIdx.x * 256 + t;
    int v = g_deg[i];
    int inc = v;
    #pragma unroll
    for (int o = 1; o < 32; o <<= 1) {
        int n = __shfl_up_sync(0xffffffffu, inc, o);
        if ((t & 31) >= o) inc += n;
    }
    if ((t & 31) == 31) wsum[t >> 5] = inc;
    __syncthreads();
    if (t < 8) {
        int w = wsum[t];
        #pragma unroll
        for (int o = 1; o < 8; o <<= 1) {
            int n = __shfl_up_sync(0xffu, w, o);
            if (t >= o) w += n;
        }
        wsum[t] = w;
    }
    __syncthreads();
    int warpoff = (t >= 32) ? wsum[(t >> 5) - 1] : 0;
    g_rowloc[i] = inc - v + warpoff;
    if (t == 0) g_boff[blockIdx.x] = atomicAdd(&g_ctr[0], wsum[7]);
}

// atomic-free CSR fill using precomputed slots
__global__ void fill_kernel(const int* __restrict__ ei) {
    int e = blockIdx.x * 256 + threadIdx.x;
    int s = __ldg(ei + e);
    int d = __ldg(ei + EE + e);
    int p = g_rowloc[d] + g_boff[d >> 8] + g_slot[e];
    g_csr[p] = s;
}

// ---------------------------------------------------------------------------
// z[n] = (1+eps)*h[n] + sum over CSR neighbors (fp16 source, fp32 accum) -> g_za.
// 256 threads, 16 threads/node, 16 nodes/block.
__global__ void __launch_bounds__(256)
gather_kernel(const float* __restrict__ eps, int layer) {
    const uint2* h2 = (const uint2*)g_xh;   // 4 halves per uint2; row = 16 uint2
    int t = threadIdx.x;
    int n = blockIdx.x * 16 + (t >> 4);
    int q = t & 15;
    int e0 = g_rowloc[n] + g_boff[n >> 8];
    int e1 = e0 + g_deg[n];
    float se = 1.0f + __ldg(eps + layer);

    uint2 r0 = __ldg(h2 + n * 16 + q);
    float2 a0 = __half22float2(*(__half2*)&r0.x);
    float2 a1 = __half22float2(*(__half2*)&r0.y);
    float4 acc = make_float4(a0.x * se, a0.y * se, a1.x * se, a1.y * se);

    int e = e0;
    for (; e + 4 <= e1; e += 4) {
        int n0 = g_csr[e],     n1 = g_csr[e + 1];
        int n2 = g_csr[e + 2], n3 = g_csr[e + 3];
        uint2 u0 = __ldg(h2 + n0 * 16 + q);
        uint2 u1 = __ldg(h2 + n1 * 16 + q);
        uint2 u2 = __ldg(h2 + n2 * 16 + q);
        uint2 u3 = __ldg(h2 + n3 * 16 + q);
        float2 f;
        f = __half22float2(*(__half2*)&u0.x); acc.x += f.x; acc.y += f.y;
        f = __half22float2(*(__half2*)&u0.y); acc.z += f.x; acc.w += f.y;
        f = __half22float2(*(__half2*)&u1.x); acc.x += f.x; acc.y += f.y;
        f = __half22float2(*(__half2*)&u1.y); acc.z += f.x; acc.w += f.y;
        f = __half22float2(*(__half2*)&u2.x); acc.x += f.x; acc.y += f.y;
        f = __half22float2(*(__half2*)&u2.y); acc.z += f.x; acc.w += f.y;
        f = __half22float2(*(__half2*)&u3.x); acc.x += f.x; acc.y += f.y;
        f = __half22float2(*(__half2*)&u3.y); acc.z += f.x; acc.w += f.y;
    }
    for (; e < e1; e++) {
        int a = g_csr[e];
        uint2 u = __ldg(h2 + a * 16 + q);
        float2 f;
        f = __half22float2(*(__half2*)&u.x); acc.x += f.x; acc.y += f.y;
        f = __half22float2(*(__half2*)&u.y); acc.z += f.x; acc.w += f.y;
    }
    ((float4*)g_za)[n * 16 + q] = acc;
}

// ---------------------------------------------------------------------------
// out = in @ W + b with f32x2 packed FMA mainloop + fused column stats.
// BN=false: g_za -> g_y, stats -> [layer*256 + 0/64)
// BN=true:  in := relu(bn1(g_y)) on load (coeffs from [layer*256+0/64)),
//           g_y -> g_z2, stats -> [layer*256 + 128/192)
template <bool BN>
__global__ void __launch_bounds__(128)
gemm_kernel(const float* __restrict__ W, const float* __restrict__ bias,
            const float* __restrict__ gamma, const float* __restrict__ beta,
            int layer) {
    const float* in = BN ? g_y : g_za;
    float* out      = BN ? g_z2 : g_y;
    __shared__ float4 zs4[128 * 16];  // 32 KB, [row][c4 ^ (row>>3)]
    __shared__ float4 ws4[64 * 16];   // 16 KB
    int t = threadIdx.x;

    #pragma unroll
    for (int p = 0; p < 8; p++)
        ws4[t + p * 128] = __ldg(((const float4*)W) + t + p * 128);

    int c4 = t & 15;
    float4 sc, sh;
    if (BN) {
        int c0 = c4 * 4;
        float scv[4], shv[4];
        #pragma unroll
        for (int j = 0; j < 4; j++) {
            float mu  = g_stats[layer * 256 + c0 + j]      * (1.0f / NN);
            float var = g_stats[layer * 256 + 64 + c0 + j] * (1.0f / NN) - mu * mu;
            float s = __ldg(gamma + c0 + j) * rsqrtf(var + 1e-5f);
            scv[j] = s;
            shv[j] = __ldg(beta + c0 + j) - mu * s;
        }
        sc = make_float4(scv[0], scv[1], scv[2], scv[3]);
        sh = make_float4(shv[0], shv[1], shv[2], shv[3]);
    }
    const float4* in4 = (const float4*)(in + (size_t)blockIdx.x * 128 * DD);
    #pragma unroll
    for (int p = 0; p < 16; p++) {
        int row = (t >> 4) + p * 8;
        float4 v = __ldg(in4 + row * 16 + c4);
        if (BN) {
            v.x = fmaxf(fmaf(v.x, sc.x, sh.x), 0.f);
            v.y = fmaxf(fmaf(v.y, sc.y, sh.y), 0.f);
            v.z = fmaxf(fmaf(v.z, sc.z, sh.z), 0.f);
            v.w = fmaxf(fmaf(v.w, sc.w, sh.w), 0.f);
        }
        zs4[row * 16 + (c4 ^ p)] = v;   // row>>3 == p
    }
    __syncthreads();

    int tr = t >> 3, tc = t & 7;
    int rbase = tr * 8;
    u64 acc2[8][4];
    #pragma unroll
    for (int i = 0; i < 8; i++)
        #pragma unroll
        for (int j = 0; j < 4; j++) acc2[i][j] = 0ull;

    #pragma unroll
    for (int kc = 0; kc < 16; kc++) {
        u64 b2[4][4];
        #pragma unroll
        for (int kk = 0; kk < 4; kk++) {
            const ulonglong2* wp = (const ulonglong2*)(ws4 + (kc * 4 + kk) * 16 + tc * 2);
            ulonglong2 p0 = wp[0];
            ulonglong2 p1 = wp[1];
            b2[kk][0] = p0.x; b2[kk][1] = p0.y;
            b2[kk][2] = p1.x; b2[kk][3] = p1.y;
        }
        #pragma unroll
        for (int ri = 0; ri < 8; ri++) {
            float4 a = zs4[(rbase + ri) * 16 + (kc ^ tr)];  // row>>3 == tr
            u64 d0, d1, d2, d3;
            asm("mov.b64 %0, {%1, %1};" : "=l"(d0) : "r"(__float_as_uint(a.x)));
            asm("mov.b64 %0, {%1, %1};" : "=l"(d1) : "r"(__float_as_uint(a.y)));
            asm("mov.b64 %0, {%1, %1};" : "=l"(d2) : "r"(__float_as_uint(a.z)));
            asm("mov.b64 %0, {%1, %1};" : "=l"(d3) : "r"(__float_as_uint(a.w)));
            #pragma unroll
            for (int j = 0; j < 4; j++) {
                asm("fma.rn.f32x2 %0, %1, %2, %0;" : "+l"(acc2[ri][j]) : "l"(d0), "l"(b2[0][j]));
                asm("fma.rn.f32x2 %0, %1, %2, %0;" : "+l"(acc2[ri][j]) : "l"(d1), "l"(b2[1][j]));
                asm("fma.rn.f32x2 %0, %1, %2, %0;" : "+l"(acc2[ri][j]) : "l"(d2), "l"(b2[2][j]));
                asm("fma.rn.f32x2 %0, %1, %2, %0;" : "+l"(acc2[ri][j]) : "l"(d3), "l"(b2[3][j]));
            }
        }
    }

    float4 bb0 = __ldg(((const float4*)bias) + tc * 2);
    float4 bb1 = __ldg(((const float4*)bias) + tc * 2 + 1);
    float bbv[8] = {bb0.x, bb0.y, bb0.z, bb0.w, bb1.x, bb1.y, bb1.z, bb1.w};
    float cs[8], cq[8];
    #pragma unroll
    for (int j = 0; j < 8; j++) { cs[j] = 0.f; cq[j] = 0.f; }
    #pragma unroll
    for (int ri = 0; ri < 8; ri++) {
        int row = rbase + ri;
        float o[8];
        #pragma unroll
        for (int j = 0; j < 4; j++) {
            unsigned lo, hi;
            asm("mov.b64 {%0, %1}, %2;" : "=r"(lo), "=r"(hi) : "l"(acc2[ri][j]));
            o[2 * j]     = __uint_as_float(lo) + bbv[2 * j];
            o[2 * j + 1] = __uint_as_float(hi) + bbv[2 * j + 1];
        }
        float* op = out + ((size_t)blockIdx.x * 128 + row) * DD + tc * 8;
        *(float4*)op       = make_float4(o[0], o[1], o[2], o[3]);
        *(float4*)(op + 4) = make_float4(o[4], o[5], o[6], o[7]);
        #pragma unroll
        for (int j = 0; j < 8; j++) {
            cs[j] += o[j];
            cq[j] += o[j] * o[j];
        }
    }

    __syncthreads();  // reuse zs4 as reduction buffer
    float* red = (float*)zs4;
    #pragma unroll
    for (int j = 0; j < 8; j++) {
        red[tr * 64 + tc * 8 + j]        = cs[j];
        red[1024 + tr * 64 + tc * 8 + j] = cq[j];
    }
    __syncthreads();
    if (t < 64) {
        float s1 = 0.f, s2 = 0.f;
        #pragma unroll
        for (int g = 0; g < 16; g++) {
            s1 += red[g * 64 + t];
            s2 += red[1024 + g * 64 + t];
        }
        int off = layer * 256 + (BN ? 128 : 0);
        atomicAdd(&g_stats[off + t], s1);
        atomicAdd(&g_stats[off + 64 + t], s2);
    }
}

// ---------------------------------------------------------------------------
// h = relu(bn2(g_z2)); segment-max into out[:, layer*64 : layer*64+64].
// LAST=false: also store h as fp16 into g_xh (next layer's gather source).
template <bool LAST>
__global__ void __launch_bounds__(256)
apply_kernel(const int* __restrict__ n2s, float* __restrict__ out,
             const float* __restrict__ gamma, const float* __restrict__ beta,
             int layer) {
    __shared__ float red[16 * DD];
    __shared__ float ssc[64], ssh[64];
    int t = threadIdx.x, b = blockIdx.x;
    if (t < 64) {
        float mu  = g_stats[layer * 256 + 128 + t] * (1.0f / NN);
        float var = g_stats[layer * 256 + 192 + t] * (1.0f / NN) - mu * mu;
        float s = __ldg(gamma + t) * rsqrtf(var + 1e-5f);
        ssc[t] = s;
        ssh[t] = __ldg(beta + t) - mu * s;
    }
    __syncthreads();

    int g = t >> 4, q = t & 15;
    int c0 = q * 4;
    float s0 = ssc[c0], s1 = ssc[c0 + 1], s2 = ssc[c0 + 2], s3 = ssc[c0 + 3];
    float h0 = ssh[c0], h1 = ssh[c0 + 1], h2 = ssh[c0 + 2], h3 = ssh[c0 + 3];

    float4 m = make_float4(0.f, 0.f, 0.f, 0.f);
    #pragma unroll
    for (int p = 0; p < 4; p++) {
        int row = b * 64 + p * 16 + g;
        float4 v = *(const float4*)(g_z2 + (size_t)row * DD + c0);
        v.x = fmaxf(fmaf(v.x, s0, h0), 0.f);
        v.y = fmaxf(fmaf(v.y, s1, h1), 0.f);
        v.z = fmaxf(fmaf(v.z, s2, h2), 0.f);
        v.w = fmaxf(fmaf(v.w, s3, h3), 0.f);
        if (!LAST) {
            uint2 r;
            *(__half2*)&r.x = __floats2half2_rn(v.x, v.y);
            *(__half2*)&r.y = __floats2half2_rn(v.z, v.w);
            ((uint2*)g_xh)[row * 16 + q] = r;
        }
        m.x = fmaxf(m.x, v.x); m.y = fmaxf(m.y, v.y);
        m.z = fmaxf(m.z, v.z); m.w = fmaxf(m.w, v.w);
    }
    red[g * DD + c0 + 0] = m.x; red[g * DD + c0 + 1] = m.y;
    red[g * DD + c0 + 2] = m.z; red[g * DD + c0 + 3] = m.w;
    __syncthreads();

    if (t < DD) {
        float mv = red[t];
        #pragma unroll
        for (int gg = 1; gg < 16; gg++) mv = fmaxf(mv, red[gg * DD + t]);
        int sA = __ldg(n2s + b * 64), sB = __ldg(n2s + b * 64 + 63);
        if (sA == sB) {
            unsigned* p = (unsigned*)(out + (size_t)sA * 128 + layer * 64 + t);
            asm volatile("red.global.max.u32 [%0], %1;"
                         :: "l"(p), "r"(__float_as_uint(mv)) : "memory");
        } else {
            // correctness fallback: per-row segment max (recompute bn on the fly)
            for (int r = 0; r < 64; r++) {
                int seg = __ldg(n2s + b * 64 + r);
                float zv = g_z2[((size_t)b * 64 + r) * DD + t];
                float v = fmaxf(fmaf(zv, ssc[t], ssh[t]), 0.f);
                unsigned* p = (unsigned*)(out + (size_t)seg * 128 + layer * 64 + t);
                asm volatile("red.global.max.u32 [%0], %1;"
                             :: "l"(p), "r"(__float_as_uint(v)) : "memory");
            }
        }
    }
}

// ---------------------------------------------------------------------------
extern "C" void kernel_launch(void* const* d_in, const int* in_sizes, int n_in,
                              void* d_out, int out_size) {
    const float* x   = (const float*)d_in[0];
    const int*   ei  = (const int*)d_in[1];
    const int*   n2s = (const int*)d_in[2];
    const float* eps = (const float*)d_in[3];
    const float* W1  = (const float*)d_in[4];
    const float* b1  = (const float*)d_in[5];
    const float* gm  = (const float*)d_in[6];
    const float* bm  = (const float*)d_in[7];
    const float* W2  = (const float*)d_in[8];
    const float* b2  = (const float*)d_in[9];
    const float* go  = (const float*)d_in[10];
    const float* bo  = (const float*)d_in[11];
    float* out = (float*)d_out;

    init_kernel<<<NN * DD / 4 / 256, 256>>>(out, x);
    count_slot_kernel<<<EE / 256, 256>>>(ei);
    scan_alloc_kernel<<<NN / 256, 256>>>();
    fill_kernel<<<EE / 256, 256>>>(ei);

    for (int l = 0; l < 2; l++) {
        gather_kernel<<<NN / 16, 256>>>(eps, l);
        gemm_kernel<false><<<NN / 128, 128>>>(W1 + l * DD * DD, b1 + l * DD,
                                              nullptr, nullptr, l);
        gemm_kernel<true><<<NN / 128, 128>>>(W2 + l * DD * DD, b2 + l * DD,
                                             gm + l * DD, bm + l * DD, l);
        if (l == 0)
            apply_kernel<false><<<NN / 64, 256>>>(n2s, out, go, bo, 0);
        else
            apply_kernel<true><<<NN / 64, 256>>>(n2s, out, go + DD, bo + DD, 1);
    }
}

// round 14
// speedup vs baseline: 1.3387x; 1.2709x over previous
#include <cuda_runtime.h>
#include <cuda_fp16.h>
#include <cstdint>

#define NN 65536
#define DD 64
#define EE 1048576
#define SS 1024

// Scratch (device globals — no allocation allowed)
__device__ __half g_xh[NN * DD];  // fp16 gather source: x (layer 0) then h (layer 1)
__device__ float g_za[NN * DD];   // gather output (z), gemm1 input
__device__ float g_y[NN * DD];    // gemm1 output, gemm2 input
__device__ float g_z2[NN * DD];   // gemm2 output (pre-BN2)
// per-layer stats: layer l uses [l*256 .. l*256+256):
//   [+0:+64) sum1, [+64:+128) sumsq1   (gemm1 output stats)
//   [+128:+192) sum2, [+192:+256) sumsq2 (gemm2 output stats)
__device__ float g_stats[512];
__device__ int   g_deg[NN];
__device__ int   g_rowloc[NN];    // block-local exclusive prefix
__device__ int   g_slot[EE];      // within-node slot per edge (from count)
__device__ int   g_csr[EE];
__device__ int   g_boff[256];     // per-block CSR region base (atomic-allocated)
__device__ int   g_ctr[1];

__device__ __forceinline__ uint32_t f2tf32(float f) {
    uint32_t r;
    asm("cvt.rna.tf32.f32 %0, %1;" : "=r"(r) : "f"(f));
    return r;
}

// ---------------------------------------------------------------------------
// grid 4096 x 256: convert x -> fp16 cache; zero out/deg/stats/ctr
__global__ void init_kernel(float* __restrict__ out, const float* __restrict__ x) {
    int i = blockIdx.x * 256 + threadIdx.x;              // 0 .. 1048575 (uint2 idx)
    float4 v = __ldg(((const float4*)x) + i);
    uint2 r;
    *(__half2*)&r.x = __floats2half2_rn(v.x, v.y);
    *(__half2*)&r.y = __floats2half2_rn(v.z, v.w);
    ((uint2*)g_xh)[i] = r;
    if (i < SS * 128 / 4) ((float4*)out)[i] = make_float4(0.f, 0.f, 0.f, 0.f);
    if (i < NN / 4) ((int4*)g_deg)[i] = make_int4(0, 0, 0, 0);
    if (i < 512) g_stats[i] = 0.f;
    if (i == 0) g_ctr[0] = 0;
}

// count degrees AND record each edge's within-node slot (coalesced store)
__global__ void count_slot_kernel(const int* __restrict__ ei) {
    int e = blockIdx.x * 256 + threadIdx.x;
    g_slot[e] = atomicAdd(&g_deg[__ldg(ei + EE + e)], 1);
}

// per-block (256 elems) exclusive scan; block CSR region base via atomicAdd
__global__ void scan_alloc_kernel() {
    __shared__ int wsum[8];
    int t = threadIdx.x;
    int i = blockIdx.x * 256 + t;
    int v = g_deg[i];
    int inc = v;
    #pragma unroll
    for (int o = 1; o < 32; o <<= 1) {
        int n = __shfl_up_sync(0xffffffffu, inc, o);
        if ((t & 31) >= o) inc += n;
    }
    if ((t & 31) == 31) wsum[t >> 5] = inc;
    __syncthreads();
    if (t < 8) {
        int w = wsum[t];
        #pragma unroll
        for (int o = 1; o < 8; o <<= 1) {
            int n = __shfl_up_sync(0xffu, w, o);
            if (t >= o) w += n;
        }
        wsum[t] = w;
    }
    __syncthreads();
    int warpoff = (t >= 32) ? wsum[(t >> 5) - 1] : 0;
    g_rowloc[i] = inc - v + warpoff;
    if (t == 0) g_boff[blockIdx.x] = atomicAdd(&g_ctr[0], wsum[7]);
}

// atomic-free CSR fill using precomputed slots
__global__ void fill_kernel(const int* __restrict__ ei) {
    int e = blockIdx.x * 256 + threadIdx.x;
    int s = __ldg(ei + e);
    int d = __ldg(ei + EE + e);
    int p = g_rowloc[d] + g_boff[d >> 8] + g_slot[e];
    g_csr[p] = s;
}

// ---------------------------------------------------------------------------
// z[n] = (1+eps)*h[n] + sum over CSR neighbors (fp16 source, fp32 accum) -> g_za.
__global__ void __launch_bounds__(256)
gather_kernel(const float* __restrict__ eps, int layer) {
    const uint2* h2 = (const uint2*)g_xh;   // 4 halves per uint2; row = 16 uint2
    int t = threadIdx.x;
    int n = blockIdx.x * 16 + (t >> 4);
    int q = t & 15;
    int e0 = g_rowloc[n] + g_boff[n >> 8];
    int e1 = e0 + g_deg[n];
    float se = 1.0f + __ldg(eps + layer);

    uint2 r0 = __ldg(h2 + n * 16 + q);
    float2 a0 = __half22float2(*(__half2*)&r0.x);
    float2 a1 = __half22float2(*(__half2*)&r0.y);
    float4 acc = make_float4(a0.x * se, a0.y * se, a1.x * se, a1.y * se);

    int e = e0;
    for (; e + 4 <= e1; e += 4) {
        int n0 = g_csr[e],     n1 = g_csr[e + 1];
        int n2 = g_csr[e + 2], n3 = g_csr[e + 3];
        uint2 u0 = __ldg(h2 + n0 * 16 + q);
        uint2 u1 = __ldg(h2 + n1 * 16 + q);
        uint2 u2 = __ldg(h2 + n2 * 16 + q);
        uint2 u3 = __ldg(h2 + n3 * 16 + q);
        float2 f;
        f = __half22float2(*(__half2*)&u0.x); acc.x += f.x; acc.y += f.y;
        f = __half22float2(*(__half2*)&u0.y); acc.z += f.x; acc.w += f.y;
        f = __half22float2(*(__half2*)&u1.x); acc.x += f.x; acc.y += f.y;
        f = __half22float2(*(__half2*)&u1.y); acc.z += f.x; acc.w += f.y;
        f = __half22float2(*(__half2*)&u2.x); acc.x += f.x; acc.y += f.y;
        f = __half22float2(*(__half2*)&u2.y); acc.z += f.x; acc.w += f.y;
        f = __half22float2(*(__half2*)&u3.x); acc.x += f.x; acc.y += f.y;
        f = __half22float2(*(__half2*)&u3.y); acc.z += f.x; acc.w += f.y;
    }
    for (; e < e1; e++) {
        int a = g_csr[e];
        uint2 u = __ldg(h2 + a * 16 + q);
        float2 f;
        f = __half22float2(*(__half2*)&u.x); acc.x += f.x; acc.y += f.y;
        f = __half22float2(*(__half2*)&u.y); acc.z += f.x; acc.w += f.y;
    }
    ((float4*)g_za)[n * 16 + q] = acc;
}

// ---------------------------------------------------------------------------
// out = in @ W + b via tf32 mma.sync (m16n8k8), fp32 accumulate, fused stats.
// BN=false: g_za -> g_y, stats -> [layer*256 + 0/64)
// BN=true:  in := relu(bn1(g_y)) on load, g_y -> g_z2, stats -> [layer*256+128/192)
// Swizzle: element (row, col) of a 64-wide tile lives at row*64 + (col ^ ((row&7)<<2)).
template <bool BN>
__global__ void __launch_bounds__(128)
gemm_kernel(const float* __restrict__ W, const float* __restrict__ bias,
            const float* __restrict__ gamma, const float* __restrict__ beta,
            int layer) {
    const float* in = BN ? g_y : g_za;
    float* out      = BN ? g_z2 : g_y;
    __shared__ uint32_t As[128 * 64];  // 32 KB, tf32 bits, swizzled
    __shared__ uint32_t Ws[64 * 64];   // 16 KB, tf32 bits, swizzled
    int t = threadIdx.x;

    // --- W fill (row-major, swizzled, tf32-converted) ---
    #pragma unroll
    for (int p = 0; p < 8; p++) {
        int idx = t + p * 128;
        int k = idx >> 4, kc4 = idx & 15;
        float4 v = __ldg(((const float4*)W) + idx);
        uint4 u = make_uint4(f2tf32(v.x), f2tf32(v.y), f2tf32(v.z), f2tf32(v.w));
        ((uint4*)Ws)[k * 16 + (kc4 ^ (k & 7))] = u;
    }

    // --- BN coefficients (per-thread, registers) ---
    int c4 = t & 15;
    float4 sc, sh;
    if (BN) {
        int c0 = c4 * 4;
        float scv[4], shv[4];
        #pragma unroll
        for (int j = 0; j < 4; j++) {
            float mu  = g_stats[layer * 256 + c0 + j]      * (1.0f / NN);
            float var = g_stats[layer * 256 + 64 + c0 + j] * (1.0f / NN) - mu * mu;
            float s = __ldg(gamma + c0 + j) * rsqrtf(var + 1e-5f);
            scv[j] = s;
            shv[j] = __ldg(beta + c0 + j) - mu * s;
        }
        sc = make_float4(scv[0], scv[1], scv[2], scv[3]);
        sh = make_float4(shv[0], shv[1], shv[2], shv[3]);
    }

    // --- A fill (BN/ReLU on load, swizzled, tf32-converted) ---
    const float4* in4 = (const float4*)(in + (size_t)blockIdx.x * 128 * DD);
    #pragma unroll
    for (int p = 0; p < 16; p++) {
        int row = (t >> 4) + p * 8;   // row & 7 == t >> 4
        float4 v = __ldg(in4 + row * 16 + c4);
        if (BN) {
            v.x = fmaxf(fmaf(v.x, sc.x, sh.x), 0.f);
            v.y = fmaxf(fmaf(v.y, sc.y, sh.y), 0.f);
            v.z = fmaxf(fmaf(v.z, sc.z, sh.z), 0.f);
            v.w = fmaxf(fmaf(v.w, sc.w, sh.w), 0.f);
        }
        uint4 u = make_uint4(f2tf32(v.x), f2tf32(v.y), f2tf32(v.z), f2tf32(v.w));
        ((uint4*)As)[row * 16 + (c4 ^ (row & 7))] = u;
    }
    __syncthreads();

    // --- mainloop: 2 m-tiles x 8 n-tiles per warp, 8 k-steps ---
    int lane = t & 31, warp = t >> 5;
    int g = lane >> 2, tig = lane & 3;
    int rbase = warp * 32;
    float c[2][8][4];
    #pragma unroll
    for (int m = 0; m < 2; m++)
        #pragma unroll
        for (int n = 0; n < 8; n++)
            #pragma unroll
            for (int j = 0; j < 4; j++) c[m][n][j] = 0.f;

    int swa = g << 2;  // (row & 7) << 2 for all 4 A rows (g, g+8, +16m)
    #pragma unroll
    for (int k8 = 0; k8 < 64; k8 += 8) {
        uint32_t a[2][4];
        #pragma unroll
        for (int m = 0; m < 2; m++) {
            int r0 = (rbase + m * 16 + g) * 64;
            int r1 = r0 + 8 * 64;
            int cA = (k8 + tig) ^ swa;
            int cB = (k8 + tig + 4) ^ swa;
            a[m][0] = As[r0 + cA];
            a[m][1] = As[r1 + cA];
            a[m][2] = As[r0 + cB];
            a[m][3] = As[r1 + cB];
        }
        #pragma unroll
        for (int n = 0; n < 8; n++) {
            int nc = n * 8 + g;
            uint32_t b0 = Ws[(k8 + tig) * 64 + (nc ^ (tig << 2))];
            uint32_t b1 = Ws[(k8 + tig + 4) * 64 + (nc ^ ((tig + 4) << 2))];
            #pragma unroll
            for (int m = 0; m < 2; m++) {
                asm("mma.sync.aligned.m16n8k8.row.col.f32.tf32.tf32.f32 "
                    "{%0,%1,%2,%3}, {%4,%5,%6,%7}, {%8,%9}, {%0,%1,%2,%3};"
                    : "+f"(c[m][n][0]), "+f"(c[m][n][1]),
                      "+f"(c[m][n][2]), "+f"(c[m][n][3])
                    : "r"(a[m][0]), "r"(a[m][1]), "r"(a[m][2]), "r"(a[m][3]),
                      "r"(b0), "r"(b1));
            }
        }
    }

    // --- epilogue: bias, store, per-column stats ---
    float cs[8][2], cq[8][2];
    #pragma unroll
    for (int n = 0; n < 8; n++) {
        cs[n][0] = cs[n][1] = 0.f;
        cq[n][0] = cq[n][1] = 0.f;
    }
    size_t obase = (size_t)blockIdx.x * 128;
    #pragma unroll
    for (int n = 0; n < 8; n++) {
        int col = n * 8 + 2 * tig;
        float2 bb = __ldg((const float2*)(bias + col));
        #pragma unroll
        for (int m = 0; m < 2; m++) {
            int r0 = rbase + m * 16 + g;
            float2 v0 = make_float2(c[m][n][0] + bb.x, c[m][n][1] + bb.y);
            float2 v1 = make_float2(c[m][n][2] + bb.x, c[m][n][3] + bb.y);
            *(float2*)(out + (obase + r0) * DD + col)     = v0;
            *(float2*)(out + (obase + r0 + 8) * DD + col) = v1;
            cs[n][0] += v0.x + v1.x;      cs[n][1] += v0.y + v1.y;
            cq[n][0] += v0.x * v0.x + v1.x * v1.x;
            cq[n][1] += v0.y * v0.y + v1.y * v1.y;
        }
    }
    // reduce over the 8 g-lane groups (lane stride 4)
    #pragma unroll
    for (int n = 0; n < 8; n++)
        #pragma unroll
        for (int j = 0; j < 2; j++) {
            cs[n][j] += __shfl_xor_sync(0xffffffffu, cs[n][j], 4);
            cs[n][j] += __shfl_xor_sync(0xffffffffu, cs[n][j], 8);
            cs[n][j] += __shfl_xor_sync(0xffffffffu, cs[n][j], 16);
            cq[n][j] += __shfl_xor_sync(0xffffffffu, cq[n][j], 4);
            cq[n][j] += __shfl_xor_sync(0xffffffffu, cq[n][j], 8);
            cq[n][j] += __shfl_xor_sync(0xffffffffu, cq[n][j], 16);
        }
    __syncthreads();           // done reading As/Ws; reuse As as reduction buffer
    float* red = (float*)As;   // [0:256) sums, [256:512) sumsqs
    if (lane < 4) {
        #pragma unroll
        for (int n = 0; n < 8; n++) {
            int col = n * 8 + 2 * lane;
            red[warp * 64 + col]           = cs[n][0];
            red[warp * 64 + col + 1]       = cs[n][1];
            red[256 + warp * 64 + col]     = cq[n][0];
            red[256 + warp * 64 + col + 1] = cq[n][1];
        }
    }
    __syncthreads();
    if (t < 64) {
        float s1 = red[t] + red[64 + t] + red[128 + t] + red[192 + t];
        float s2 = red[256 + t] + red[320 + t] + red[384 + t] + red[448 + t];
        int off = layer * 256 + (BN ? 128 : 0);
        atomicAdd(&g_stats[off + t], s1);
        atomicAdd(&g_stats[off + 64 + t], s2);
    }
}

// ---------------------------------------------------------------------------
// h = relu(bn2(g_z2)); segment-max into out[:, layer*64 : layer*64+64].
// LAST=false: also store h as fp16 into g_xh (next layer's gather source).
template <bool LAST>
__global__ void __launch_bounds__(256)
apply_kernel(const int* __restrict__ n2s, float* __restrict__ out,
             const float* __restrict__ gamma, const float* __restrict__ beta,
             int layer) {
    __shared__ float red[16 * DD];
    __shared__ float ssc[64], ssh[64];
    int t = threadIdx.x, b = blockIdx.x;
    if (t < 64) {
        float mu  = g_stats[layer * 256 + 128 + t] * (1.0f / NN);
        float var = g_stats[layer * 256 + 192 + t] * (1.0f / NN) - mu * mu;
        float s = __ldg(gamma + t) * rsqrtf(var + 1e-5f);
        ssc[t] = s;
        ssh[t] = __ldg(beta + t) - mu * s;
    }
    __syncthreads();

    int g = t >> 4, q = t & 15;
    int c0 = q * 4;
    float s0 = ssc[c0], s1 = ssc[c0 + 1], s2 = ssc[c0 + 2], s3 = ssc[c0 + 3];
    float h0 = ssh[c0], h1 = ssh[c0 + 1], h2 = ssh[c0 + 2], h3 = ssh[c0 + 3];

    float4 m = make_float4(0.f, 0.f, 0.f, 0.f);
    #pragma unroll
    for (int p = 0; p < 4; p++) {
        int row = b * 64 + p * 16 + g;
        float4 v = *(const float4*)(g_z2 + (size_t)row * DD + c0);
        v.x = fmaxf(fmaf(v.x, s0, h0), 0.f);
        v.y = fmaxf(fmaf(v.y, s1, h1), 0.f);
        v.z = fmaxf(fmaf(v.z, s2, h2), 0.f);
        v.w = fmaxf(fmaf(v.w, s3, h3), 0.f);
        if (!LAST) {
            uint2 r;
            *(__half2*)&r.x = __floats2half2_rn(v.x, v.y);
            *(__half2*)&r.y = __floats2half2_rn(v.z, v.w);
            ((uint2*)g_xh)[row * 16 + q] = r;
        }
        m.x = fmaxf(m.x, v.x); m.y = fmaxf(m.y, v.y);
        m.z = fmaxf(m.z, v.z); m.w = fmaxf(m.w, v.w);
    }
    red[g * DD + c0 + 0] = m.x; red[g * DD + c0 + 1] = m.y;
    red[g * DD + c0 + 2] = m.z; red[g * DD + c0 + 3] = m.w;
    __syncthreads();

    if (t < DD) {
        float mv = red[t];
        #pragma unroll
        for (int gg = 1; gg < 16; gg++) mv = fmaxf(mv, red[gg * DD + t]);
        int sA = __ldg(n2s + b * 64), sB = __ldg(n2s + b * 64 + 63);
        if (sA == sB) {
            unsigned* p = (unsigned*)(out + (size_t)sA * 128 + layer * 64 + t);
            asm volatile("red.global.max.u32 [%0], %1;"
                         :: "l"(p), "r"(__float_as_uint(mv)) : "memory");
        } else {
            // correctness fallback: per-row segment max (recompute bn on the fly)
            for (int r = 0; r < 64; r++) {
                int seg = __ldg(n2s + b * 64 + r);
                float zv = g_z2[((size_t)b * 64 + r) * DD + t];
                float v = fmaxf(fmaf(zv, ssc[t], ssh[t]), 0.f);
                unsigned* p = (unsigned*)(out + (size_t)seg * 128 + layer * 64 + t);
                asm volatile("red.global.max.u32 [%0], %1;"
                             :: "l"(p), "r"(__float_as_uint(v)) : "memory");
            }
        }
    }
}

// ---------------------------------------------------------------------------
extern "C" void kernel_launch(void* const* d_in, const int* in_sizes, int n_in,
                              void* d_out, int out_size) {
    const float* x   = (const float*)d_in[0];
    const int*   ei  = (const int*)d_in[1];
    const int*   n2s = (const int*)d_in[2];
    const float* eps = (const float*)d_in[3];
    const float* W1  = (const float*)d_in[4];
    const float* b1  = (const float*)d_in[5];
    const float* gm  = (const float*)d_in[6];
    const float* bm  = (const float*)d_in[7];
    const float* W2  = (const float*)d_in[8];
    const float* b2  = (const float*)d_in[9];
    const float* go  = (const float*)d_in[10];
    const float* bo  = (const float*)d_in[11];
    float* out = (float*)d_out;

    init_kernel<<<NN * DD / 4 / 256, 256>>>(out, x);
    count_slot_kernel<<<EE / 256, 256>>>(ei);
    scan_alloc_kernel<<<NN / 256, 256>>>();
    fill_kernel<<<EE / 256, 256>>>(ei);

    for (int l = 0; l < 2; l++) {
        gather_kernel<<<NN / 16, 256>>>(eps, l);
        gemm_kernel<false><<<NN / 128, 128>>>(W1 + l * DD * DD, b1 + l * DD,
                                              nullptr, nullptr, l);
        gemm_kernel<true><<<NN / 128, 128>>>(W2 + l * DD * DD, b2 + l * DD,
                                             gm + l * DD, bm + l * DD, l);
        if (l == 0)
            apply_kernel<false><<<NN / 64, 256>>>(n2s, out, go, bo, 0);
        else
            apply_kernel<true><<<NN / 64, 256>>>(n2s, out, go + DD, bo + DD, 1);
    }
}

// round 16
// speedup vs baseline: 1.3391x; 1.0003x over previous
#include <cuda_runtime.h>
#include <cuda_fp16.h>
#include <cstdint>

#define NN 65536
#define DD 64
#define EE 1048576
#define SS 1024

// Scratch (device globals — no allocation allowed)
__device__ __half g_xh[NN * DD];  // fp16 gather source: x (layer 0) then h (layer 1)
__device__ __half g_za[NN * DD];  // fp16 gather output (z), gemm1 input
__device__ float g_y[NN * DD];    // gemm1 output, gemm2 input (fp32)
__device__ float g_z2[NN * DD];   // gemm2 output (pre-BN2)
// per-layer stats: layer l uses [l*256 .. l*256+256):
//   [+0:+64) sum1, [+64:+128) sumsq1   (gemm1 output stats)
//   [+128:+192) sum2, [+192:+256) sumsq2 (gemm2 output stats)
__device__ float g_stats[512];
__device__ int   g_deg[NN];
__device__ int   g_rowabs[NN];    // absolute CSR row base per node
__device__ int   g_fill[NN];
__device__ int   g_slot[EE];      // within-node slot per edge (from count)
__device__ unsigned short g_csr[EE];  // uint16 node ids (NN = 65536 fits exactly)
__device__ int   g_ctr[1];

__device__ __forceinline__ uint32_t f2tf32(float f) {
    uint32_t r;
    asm("cvt.rna.tf32.f32 %0, %1;" : "=r"(r) : "f"(f));
    return r;
}

// ---------------------------------------------------------------------------
// grid 4096 x 256: convert x -> fp16 cache; zero out/deg/stats/ctr
__global__ void init_kernel(float* __restrict__ out, const float* __restrict__ x) {
    int i = blockIdx.x * 256 + threadIdx.x;              // 0 .. 1048575 (uint2 idx)
    float4 v = __ldg(((const float4*)x) + i);
    uint2 r;
    *(__half2*)&r.x = __floats2half2_rn(v.x, v.y);
    *(__half2*)&r.y = __floats2half2_rn(v.z, v.w);
    ((uint2*)g_xh)[i] = r;
    if (i < SS * 128 / 4) ((float4*)out)[i] = make_float4(0.f, 0.f, 0.f, 0.f);
    if (i < NN / 4) ((int4*)g_deg)[i] = make_int4(0, 0, 0, 0);
    if (i < 512) g_stats[i] = 0.f;
    if (i == 0) g_ctr[0] = 0;
}

// count degrees AND record each edge's within-node slot (coalesced store)
__global__ void count_slot_kernel(const int* __restrict__ ei) {
    int e = blockIdx.x * 256 + threadIdx.x;
    g_slot[e] = atomicAdd(&g_deg[__ldg(ei + EE + e)], 1);
}

// per-block (256 elems) exclusive scan; block base via atomicAdd, broadcast,
// and ABSOLUTE row offsets written out (no second indirection downstream).
__global__ void scan_alloc_kernel() {
    __shared__ int wsum[8];
    __shared__ int bbase;
    int t = threadIdx.x;
    int i = blockIdx.x * 256 + t;
    int v = g_deg[i];
    int inc = v;
    #pragma unroll
    for (int o = 1; o < 32; o <<= 1) {
        int n = __shfl_up_sync(0xffffffffu, inc, o);
        if ((t & 31) >= o) inc += n;
    }
    if ((t & 31) == 31) wsum[t >> 5] = inc;
    __syncthreads();
    if (t < 8) {
        int w = wsum[t];
        #pragma unroll
        for (int o = 1; o < 8; o <<= 1) {
            int n = __shfl_up_sync(0xffu, w, o);
            if (t >= o) w += n;
        }
        wsum[t] = w;
    }
    __syncthreads();
    if (t == 0) bbase = atomicAdd(&g_ctr[0], wsum[7]);
    int warpoff = (t >= 32) ? wsum[(t >> 5) - 1] : 0;
    __syncthreads();
    int a = inc - v + warpoff + bbase;
    g_rowabs[i] = a;
    g_fill[i]   = a;
}

// atomic-free CSR fill using precomputed slots (uint16 payload)
__global__ void fill_kernel(const int* __restrict__ ei) {
    int e = blockIdx.x * 256 + threadIdx.x;
    int s = __ldg(ei + e);
    int d = __ldg(ei + EE + e);
    int p = g_fill[d] + g_slot[e];
    g_csr[p] = (unsigned short)s;
}

// ---------------------------------------------------------------------------
// z[n] = (1+eps)*h[n] + sum over CSR neighbors (fp16 src, fp32 accum, fp16 out).
__global__ void __launch_bounds__(256)
gather_kernel(const float* __restrict__ eps, int layer) {
    const uint2* h2 = (const uint2*)g_xh;   // 4 halves per uint2; row = 16 uint2
    int t = threadIdx.x;
    int n = blockIdx.x * 16 + (t >> 4);
    int q = t & 15;
    int e0 = g_rowabs[n];
    int e1 = e0 + g_deg[n];
    float se = 1.0f + __ldg(eps + layer);

    uint2 r0 = __ldg(h2 + n * 16 + q);
    float2 a0 = __half22float2(*(__half2*)&r0.x);
    float2 a1 = __half22float2(*(__half2*)&r0.y);
    float4 acc = make_float4(a0.x * se, a0.y * se, a1.x * se, a1.y * se);

    int e = e0;
    for (; e + 4 <= e1; e += 4) {
        int n0 = g_csr[e],     n1 = g_csr[e + 1];
        int n2 = g_csr[e + 2], n3 = g_csr[e + 3];
        uint2 u0 = __ldg(h2 + n0 * 16 + q);
        uint2 u1 = __ldg(h2 + n1 * 16 + q);
        uint2 u2 = __ldg(h2 + n2 * 16 + q);
        uint2 u3 = __ldg(h2 + n3 * 16 + q);
        float2 f;
        f = __half22float2(*(__half2*)&u0.x); acc.x += f.x; acc.y += f.y;
        f = __half22float2(*(__half2*)&u0.y); acc.z += f.x; acc.w += f.y;
        f = __half22float2(*(__half2*)&u1.x); acc.x += f.x; acc.y += f.y;
        f = __half22float2(*(__half2*)&u1.y); acc.z += f.x; acc.w += f.y;
        f = __half22float2(*(__half2*)&u2.x); acc.x += f.x; acc.y += f.y;
        f = __half22float2(*(__half2*)&u2.y); acc.z += f.x; acc.w += f.y;
        f = __half22float2(*(__half2*)&u3.x); acc.x += f.x; acc.y += f.y;
        f = __half22float2(*(__half2*)&u3.y); acc.z += f.x; acc.w += f.y;
    }
    for (; e < e1; e++) {
        int a = g_csr[e];
        uint2 u = __ldg(h2 + a * 16 + q);
        float2 f;
        f = __half22float2(*(__half2*)&u.x); acc.x += f.x; acc.y += f.y;
        f = __half22float2(*(__half2*)&u.y); acc.z += f.x; acc.w += f.y;
    }
    uint2 w;
    *(__half2*)&w.x = __floats2half2_rn(acc.x, acc.y);
    *(__half2*)&w.y = __floats2half2_rn(acc.z, acc.w);
    ((uint2*)g_za)[n * 16 + q] = w;
}

// ---------------------------------------------------------------------------
// out = in @ W + b via tf32 mma.sync (m16n8k8), fp32 accumulate, fused stats.
// BN=false: g_za (fp16) -> g_y, stats -> [layer*256 + 0/64)
// BN=true:  in := relu(bn1(g_y)) on load, g_y -> g_z2, stats -> [layer*256+128/192)
// Swizzle: element (row, col) of a 64-wide tile lives at row*64 + (col ^ ((row&7)<<2)).
template <bool BN>
__global__ void __launch_bounds__(128)
gemm_kernel(const float* __restrict__ W, const float* __restrict__ bias,
            const float* __restrict__ gamma, const float* __restrict__ beta,
            int layer) {
    float* out = BN ? g_z2 : g_y;
    __shared__ uint32_t As[128 * 64];  // 32 KB, tf32 bits, swizzled
    __shared__ uint32_t Ws[64 * 64];   // 16 KB, tf32 bits, swizzled
    int t = threadIdx.x;

    // --- W fill (row-major, swizzled, tf32-converted) ---
    #pragma unroll
    for (int p = 0; p < 8; p++) {
        int idx = t + p * 128;
        int k = idx >> 4, kc4 = idx & 15;
        float4 v = __ldg(((const float4*)W) + idx);
        uint4 u = make_uint4(f2tf32(v.x), f2tf32(v.y), f2tf32(v.z), f2tf32(v.w));
        ((uint4*)Ws)[k * 16 + (kc4 ^ (k & 7))] = u;
    }

    // --- BN coefficients (per-thread, registers) ---
    int c4 = t & 15;
    float4 sc, sh;
    if (BN) {
        int c0 = c4 * 4;
        float scv[4], shv[4];
        #pragma unroll
        for (int j = 0; j < 4; j++) {
            float mu  = g_stats[layer * 256 + c0 + j]      * (1.0f / NN);
            float var = g_stats[layer * 256 + 64 + c0 + j] * (1.0f / NN) - mu * mu;
            float s = __ldg(gamma + c0 + j) * rsqrtf(var + 1e-5f);
            scv[j] = s;
            shv[j] = __ldg(beta + c0 + j) - mu * s;
        }
        sc = make_float4(scv[0], scv[1], scv[2], scv[3]);
        sh = make_float4(shv[0], shv[1], shv[2], shv[3]);
    }

    // --- A fill (fp16 load for gemm1, fp32+BN/ReLU for gemm2; swizzled tf32) ---
    const float4* in4 = (const float4*)(g_y + (size_t)blockIdx.x * 128 * DD);
    const uint2*  in2 = ((const uint2*)g_za) + (size_t)blockIdx.x * 128 * 16;
    #pragma unroll
    for (int p = 0; p < 16; p++) {
        int row = (t >> 4) + p * 8;   // row & 7 == t >> 4
        float4 v;
        if (BN) {
            v = __ldg(in4 + row * 16 + c4);
            v.x = fmaxf(fmaf(v.x, sc.x, sh.x), 0.f);
            v.y = fmaxf(fmaf(v.y, sc.y, sh.y), 0.f);
            v.z = fmaxf(fmaf(v.z, sc.z, sh.z), 0.f);
            v.w = fmaxf(fmaf(v.w, sc.w, sh.w), 0.f);
        } else {
            uint2 u = __ldg(in2 + row * 16 + c4);
            float2 f0 = __half22float2(*(__half2*)&u.x);
            float2 f1 = __half22float2(*(__half2*)&u.y);
            v = make_float4(f0.x, f0.y, f1.x, f1.y);
        }
        uint4 u = make_uint4(f2tf32(v.x), f2tf32(v.y), f2tf32(v.z), f2tf32(v.w));
        ((uint4*)As)[row * 16 + (c4 ^ (row & 7))] = u;
    }
    __syncthreads();

    // --- mainloop: 2 m-tiles x 8 n-tiles per warp, 8 k-steps ---
    int lane = t & 31, warp = t >> 5;
    int g = lane >> 2, tig = lane & 3;
    int rbase = warp * 32;
    float c[2][8][4];
    #pragma unroll
    for (int m = 0; m < 2; m++)
        #pragma unroll
        for (int n = 0; n < 8; n++)
            #pragma unroll
            for (int j = 0; j < 4; j++) c[m][n][j] = 0.f;

    int swa = g << 2;  // (row & 7) << 2 for all 4 A rows (g, g+8, +16m)
    #pragma unroll
    for (int k8 = 0; k8 < 64; k8 += 8) {
        uint32_t a[2][4];
        #pragma unroll
        for (int m = 0; m < 2; m++) {
            int r0 = (rbase + m * 16 + g) * 64;
            int r1 = r0 + 8 * 64;
            int cA = (k8 + tig) ^ swa;
            int cB = (k8 + tig + 4) ^ swa;
            a[m][0] = As[r0 + cA];
            a[m][1] = As[r1 + cA];
            a[m][2] = As[r0 + cB];
            a[m][3] = As[r1 + cB];
        }
        #pragma unroll
        for (int n = 0; n < 8; n++) {
            int nc = n * 8 + g;
            uint32_t b0 = Ws[(k8 + tig) * 64 + (nc ^ (tig << 2))];
            uint32_t b1 = Ws[(k8 + tig + 4) * 64 + (nc ^ ((tig + 4) << 2))];
            #pragma unroll
            for (int m = 0; m < 2; m++) {
                asm("mma.sync.aligned.m16n8k8.row.col.f32.tf32.tf32.f32 "
                    "{%0,%1,%2,%3}, {%4,%5,%6,%7}, {%8,%9}, {%0,%1,%2,%3};"
                    : "+f"(c[m][n][0]), "+f"(c[m][n][1]),
                      "+f"(c[m][n][2]), "+f"(c[m][n][3])
                    : "r"(a[m][0]), "r"(a[m][1]), "r"(a[m][2]), "r"(a[m][3]),
                      "r"(b0), "r"(b1));
            }
        }
    }

    // --- epilogue: bias, store, per-column stats ---
    float cs[8][2], cq[8][2];
    #pragma unroll
    for (int n = 0; n < 8; n++) {
        cs[n][0] = cs[n][1] = 0.f;
        cq[n][0] = cq[n][1] = 0.f;
    }
    size_t obase = (size_t)blockIdx.x * 128;
    #pragma unroll
    for (int n = 0; n < 8; n++) {
        int col = n * 8 + 2 * tig;
        float2 bb = __ldg((const float2*)(bias + col));
        #pragma unroll
        for (int m = 0; m < 2; m++) {
            int r0 = rbase + m * 16 + g;
            float2 v0 = make_float2(c[m][n][0] + bb.x, c[m][n][1] + bb.y);
            float2 v1 = make_float2(c[m][n][2] + bb.x, c[m][n][3] + bb.y);
            *(float2*)(out + (obase + r0) * DD + col)     = v0;
            *(float2*)(out + (obase + r0 + 8) * DD + col) = v1;
            cs[n][0] += v0.x + v1.x;      cs[n][1] += v0.y + v1.y;
            cq[n][0] += v0.x * v0.x + v1.x * v1.x;
            cq[n][1] += v0.y * v0.y + v1.y * v1.y;
        }
    }
    // reduce over the 8 g-lane groups (lane stride 4)
    #pragma unroll
    for (int n = 0; n < 8; n++)
        #pragma unroll
        for (int j = 0; j < 2; j++) {
            cs[n][j] += __shfl_xor_sync(0xffffffffu, cs[n][j], 4);
            cs[n][j] += __shfl_xor_sync(0xffffffffu, cs[n][j], 8);
            cs[n][j] += __shfl_xor_sync(0xffffffffu, cs[n][j], 16);
            cq[n][j] += __shfl_xor_sync(0xffffffffu, cq[n][j], 4);
            cq[n][j] += __shfl_xor_sync(0xffffffffu, cq[n][j], 8);
            cq[n][j] += __shfl_xor_sync(0xffffffffu, cq[n][j], 16);
        }
    __syncthreads();           // done reading As/Ws; reuse As as reduction buffer
    float* red = (float*)As;   // [0:256) sums, [256:512) sumsqs
    if (lane < 4) {
        #pragma unroll
        for (int n = 0; n < 8; n++) {
            int col = n * 8 + 2 * lane;
            red[warp * 64 + col]           = cs[n][0];
            red[warp * 64 + col + 1]       = cs[n][1];
            red[256 + warp * 64 + col]     = cq[n][0];
            red[256 + warp * 64 + col + 1] = cq[n][1];
        }
    }
    __syncthreads();
    if (t < 64) {
        float s1 = red[t] + red[64 + t] + red[128 + t] + red[192 + t];
        float s2 = red[256 + t] + red[320 + t] + red[384 + t] + red[448 + t];
        int off = layer * 256 + (BN ? 128 : 0);
        atomicAdd(&g_stats[off + t], s1);
        atomicAdd(&g_stats[off + 64 + t], s2);
    }
}

// ---------------------------------------------------------------------------
// h = relu(bn2(g_z2)); segment-max into out[:, layer*64 : layer*64+64].
// LAST=false: also store h as fp16 into g_xh (next layer's gather source).
template <bool LAST>
__global__ void __launch_bounds__(256)
apply_kernel(const int* __restrict__ n2s, float* __restrict__ out,
             const float* __restrict__ gamma, const float* __restrict__ beta,
             int layer) {
    __shared__ float red[16 * DD];
    __shared__ float ssc[64], ssh[64];
    int t = threadIdx.x, b = blockIdx.x;
    if (t < 64) {
        float mu  = g_stats[layer * 256 + 128 + t] * (1.0f / NN);
        float var = g_stats[layer * 256 + 192 + t] * (1.0f / NN) - mu * mu;
        float s = __ldg(gamma + t) * rsqrtf(var + 1e-5f);
        ssc[t] = s;
        ssh[t] = __ldg(beta + t) - mu * s;
    }
    __syncthreads();

    int g = t >> 4, q = t & 15;
    int c0 = q * 4;
    float s0 = ssc[c0], s1 = ssc[c0 + 1], s2 = ssc[c0 + 2], s3 = ssc[c0 + 3];
    float h0 = ssh[c0], h1 = ssh[c0 + 1], h2 = ssh[c0 + 2], h3 = ssh[c0 + 3];

    float4 m = make_float4(0.f, 0.f, 0.f, 0.f);
    #pragma unroll
    for (int p = 0; p < 4; p++) {
        int row = b * 64 + p * 16 + g;
        float4 v = *(const float4*)(g_z2 + (size_t)row * DD + c0);
        v.x = fmaxf(fmaf(v.x, s0, h0), 0.f);
        v.y = fmaxf(fmaf(v.y, s1, h1), 0.f);
        v.z = fmaxf(fmaf(v.z, s2, h2), 0.f);
        v.w = fmaxf(fmaf(v.w, s3, h3), 0.f);
        if (!LAST) {
            uint2 r;
            *(__half2*)&r.x = __floats2half2_rn(v.x, v.y);
            *(__half2*)&r.y = __floats2half2_rn(v.z, v.w);
            ((uint2*)g_xh)[row * 16 + q] = r;
        }
        m.x = fmaxf(m.x, v.x); m.y = fmaxf(m.y, v.y);
        m.z = fmaxf(m.z, v.z); m.w = fmaxf(m.w, v.w);
    }
    red[g * DD + c0 + 0] = m.x; red[g * DD + c0 + 1] = m.y;
    red[g * DD + c0 + 2] = m.z; red[g * DD + c0 + 3] = m.w;
    __syncthreads();

    if (t < DD) {
        float mv = red[t];
        #pragma unroll
        for (int gg = 1; gg < 16; gg++) mv = fmaxf(mv, red[gg * DD + t]);
        int sA = __ldg(n2s + b * 64), sB = __ldg(n2s + b * 64 + 63);
        if (sA == sB) {
            unsigned* p = (unsigned*)(out + (size_t)sA * 128 + layer * 64 + t);
            asm volatile("red.global.max.u32 [%0], %1;"
                         :: "l"(p), "r"(__float_as_uint(mv)) : "memory");
        } else {
            // correctness fallback: per-row segment max (recompute bn on the fly)
            for (int r = 0; r < 64; r++) {
                int seg = __ldg(n2s + b * 64 + r);
                float zv = g_z2[((size_t)b * 64 + r) * DD + t];
                float v = fmaxf(fmaf(zv, ssc[t], ssh[t]), 0.f);
                unsigned* p = (unsigned*)(out + (size_t)seg * 128 + layer * 64 + t);
                asm volatile("red.global.max.u32 [%0], %1;"
                             :: "l"(p), "r"(__float_as_uint(v)) : "memory");
            }
        }
    }
}

// ---------------------------------------------------------------------------
extern "C" void kernel_launch(void* const* d_in, const int* in_sizes, int n_in,
                              void* d_out, int out_size) {
    const float* x   = (const float*)d_in[0];
    const int*   ei  = (const int*)d_in[1];
    const int*   n2s = (const int*)d_in[2];
    const float* eps = (const float*)d_in[3];
    const float* W1  = (const float*)d_in[4];
    const float* b1  = (const float*)d_in[5];
    const float* gm  = (const float*)d_in[6];
    const float* bm  = (const float*)d_in[7];
    const float* W2  = (const float*)d_in[8];
    const float* b2  = (const float*)d_in[9];
    const float* go  = (const float*)d_in[10];
    const float* bo  = (const float*)d_in[11];
    float* out = (float*)d_out;

    init_kernel<<<NN * DD / 4 / 256, 256>>>(out, x);
    count_slot_kernel<<<EE / 256, 256>>>(ei);
    scan_alloc_kernel<<<NN / 256, 256>>>();
    fill_kernel<<<EE / 256, 256>>>(ei);

    for (int l = 0; l < 2; l++) {
        gather_kernel<<<NN / 16, 256>>>(eps, l);
        gemm_kernel<false><<<NN / 128, 128>>>(W1 + l * DD * DD, b1 + l * DD,
                                              nullptr, nullptr, l);
        gemm_kernel<true><<<NN / 128, 128>>>(W2 + l * DD * DD, b2 + l * DD,
                                             gm + l * DD, bm + l * DD, l);
        if (l == 0)
            apply_kernel<false><<<NN / 64, 256>>>(n2s, out, go, bo, 0);
        else
            apply_kernel<true><<<NN / 64, 256>>>(n2s, out, go + DD, bo + DD, 1);
    }
}

// round 17
// speedup vs baseline: 1.3857x; 1.0348x over previous
#include <cuda_runtime.h>
#include <cuda_fp16.h>
#include <cstdint>

#define NN 65536
#define DD 64
#define EE 1048576
#define SS 1024

// Scratch (device globals — no allocation allowed)
__device__ __half g_xh[NN * DD];  // fp16 gather source: x (layer 0) then h (layer 1)
__device__ __half g_za[NN * DD];  // fp16 gather output (z), gemm1 input
__device__ float g_y[NN * DD];    // gemm1 output, gemm2 input (fp32)
__device__ float g_z2[NN * DD];   // gemm2 output (pre-BN2)
// per-layer stats: layer l uses [l*256 .. l*256+256):
//   [+0:+64) sum1, [+64:+128) sumsq1   (gemm1 output stats)
//   [+128:+192) sum2, [+192:+256) sumsq2 (gemm2 output stats)
__device__ float g_stats[512];
__device__ int   g_deg[NN];
__device__ int   g_rowabs[NN];    // absolute CSR row base per node
__device__ int   g_fill[NN];
__device__ int   g_slot[EE];      // within-node slot per edge (from count)
__device__ int   g_csr[EE];       // 32-bit node ids (u16 scattered stores were slower)
__device__ int   g_ctr[1];

__device__ __forceinline__ uint32_t f2tf32(float f) {
    uint32_t r;
    asm("cvt.rna.tf32.f32 %0, %1;" : "=r"(r) : "f"(f));
    return r;
}

// ---------------------------------------------------------------------------
// grid 4096 x 256: convert x -> fp16 cache; zero out/deg/stats/ctr
__global__ void init_kernel(float* __restrict__ out, const float* __restrict__ x) {
    int i = blockIdx.x * 256 + threadIdx.x;              // 0 .. 1048575 (uint2 idx)
    float4 v = __ldg(((const float4*)x) + i);
    uint2 r;
    *(__half2*)&r.x = __floats2half2_rn(v.x, v.y);
    *(__half2*)&r.y = __floats2half2_rn(v.z, v.w);
    ((uint2*)g_xh)[i] = r;
    if (i < SS * 128 / 4) ((float4*)out)[i] = make_float4(0.f, 0.f, 0.f, 0.f);
    if (i < NN / 4) ((int4*)g_deg)[i] = make_int4(0, 0, 0, 0);
    if (i < 512) g_stats[i] = 0.f;
    if (i == 0) g_ctr[0] = 0;
}

// count degrees AND record each edge's within-node slot (coalesced store)
__global__ void count_slot_kernel(const int* __restrict__ ei) {
    int e = blockIdx.x * 256 + threadIdx.x;
    g_slot[e] = atomicAdd(&g_deg[__ldg(ei + EE + e)], 1);
}

// per-block (256 elems) exclusive scan; block base via atomicAdd, broadcast,
// and ABSOLUTE row offsets written out (no second indirection downstream).
__global__ void scan_alloc_kernel() {
    __shared__ int wsum[8];
    __shared__ int bbase;
    int t = threadIdx.x;
    int i = blockIdx.x * 256 + t;
    int v = g_deg[i];
    int inc = v;
    #pragma unroll
    for (int o = 1; o < 32; o <<= 1) {
        int n = __shfl_up_sync(0xffffffffu, inc, o);
        if ((t & 31) >= o) inc += n;
    }
    if ((t & 31) == 31) wsum[t >> 5] = inc;
    __syncthreads();
    if (t < 8) {
        int w = wsum[t];
        #pragma unroll
        for (int o = 1; o < 8; o <<= 1) {
            int n = __shfl_up_sync(0xffu, w, o);
            if (t >= o) w += n;
        }
        wsum[t] = w;
    }
    __syncthreads();
    if (t == 0) bbase = atomicAdd(&g_ctr[0], wsum[7]);
    int warpoff = (t >= 32) ? wsum[(t >> 5) - 1] : 0;
    __syncthreads();
    int a = inc - v + warpoff + bbase;
    g_rowabs[i] = a;
    g_fill[i]   = a;
}

// atomic-free CSR fill using precomputed slots (32-bit payload)
__global__ void fill_kernel(const int* __restrict__ ei) {
    int e = blockIdx.x * 256 + threadIdx.x;
    int s = __ldg(ei + e);
    int d = __ldg(ei + EE + e);
    int p = g_fill[d] + g_slot[e];
    g_csr[p] = s;
}

// ---------------------------------------------------------------------------
// z[n] = (1+eps)*h[n] + sum over CSR neighbors (fp16 src, fp32 accum, fp16 out).
// 8 threads/node, 16B (8-half) loads; 32 nodes/block; grid NN/32.
__global__ void __launch_bounds__(256)
gather_kernel(const float* __restrict__ eps, int layer) {
    const uint4* h4 = (const uint4*)g_xh;   // 8 halves per uint4; row = 8 uint4
    int t = threadIdx.x;
    int n = blockIdx.x * 32 + (t >> 3);
    int q = t & 7;
    int e0 = g_rowabs[n];
    int e1 = e0 + g_deg[n];
    float se = 1.0f + __ldg(eps + layer);

    float acc[8];
    {
        uint4 r0 = __ldg(h4 + n * 8 + q);
        float2 f0 = __half22float2(*(__half2*)&r0.x);
        float2 f1 = __half22float2(*(__half2*)&r0.y);
        float2 f2 = __half22float2(*(__half2*)&r0.z);
        float2 f3 = __half22float2(*(__half2*)&r0.w);
        acc[0] = f0.x * se; acc[1] = f0.y * se;
        acc[2] = f1.x * se; acc[3] = f1.y * se;
        acc[4] = f2.x * se; acc[5] = f2.y * se;
        acc[6] = f3.x * se; acc[7] = f3.y * se;
    }

    int e = e0;
    for (; e + 4 <= e1; e += 4) {
        int a0 = g_csr[e],     a1 = g_csr[e + 1];
        int a2 = g_csr[e + 2], a3 = g_csr[e + 3];
        uint4 u0 = __ldg(h4 + a0 * 8 + q);
        uint4 u1 = __ldg(h4 + a1 * 8 + q);
        uint4 u2 = __ldg(h4 + a2 * 8 + q);
        uint4 u3 = __ldg(h4 + a3 * 8 + q);
        float2 f;
        f = __half22float2(*(__half2*)&u0.x); acc[0] += f.x; acc[1] += f.y;
        f = __half22float2(*(__half2*)&u0.y); acc[2] += f.x; acc[3] += f.y;
        f = __half22float2(*(__half2*)&u0.z); acc[4] += f.x; acc[5] += f.y;
        f = __half22float2(*(__half2*)&u0.w); acc[6] += f.x; acc[7] += f.y;
        f = __half22float2(*(__half2*)&u1.x); acc[0] += f.x; acc[1] += f.y;
        f = __half22float2(*(__half2*)&u1.y); acc[2] += f.x; acc[3] += f.y;
        f = __half22float2(*(__half2*)&u1.z); acc[4] += f.x; acc[5] += f.y;
        f = __half22float2(*(__half2*)&u1.w); acc[6] += f.x; acc[7] += f.y;
        f = __half22float2(*(__half2*)&u2.x); acc[0] += f.x; acc[1] += f.y;
        f = __half22float2(*(__half2*)&u2.y); acc[2] += f.x; acc[3] += f.y;
        f = __half22float2(*(__half2*)&u2.z); acc[4] += f.x; acc[5] += f.y;
        f = __half22float2(*(__half2*)&u2.w); acc[6] += f.x; acc[7] += f.y;
        f = __half22float2(*(__half2*)&u3.x); acc[0] += f.x; acc[1] += f.y;
        f = __half22float2(*(__half2*)&u3.y); acc[2] += f.x; acc[3] += f.y;
        f = __half22float2(*(__half2*)&u3.z); acc[4] += f.x; acc[5] += f.y;
        f = __half22float2(*(__half2*)&u3.w); acc[6] += f.x; acc[7] += f.y;
    }
    for (; e < e1; e++) {
        int a = g_csr[e];
        uint4 u = __ldg(h4 + a * 8 + q);
        float2 f;
        f = __half22float2(*(__half2*)&u.x); acc[0] += f.x; acc[1] += f.y;
        f = __half22float2(*(__half2*)&u.y); acc[2] += f.x; acc[3] += f.y;
        f = __half22float2(*(__half2*)&u.z); acc[4] += f.x; acc[5] += f.y;
        f = __half22float2(*(__half2*)&u.w); acc[6] += f.x; acc[7] += f.y;
    }
    uint4 w;
    *(__half2*)&w.x = __floats2half2_rn(acc[0], acc[1]);
    *(__half2*)&w.y = __floats2half2_rn(acc[2], acc[3]);
    *(__half2*)&w.z = __floats2half2_rn(acc[4], acc[5]);
    *(__half2*)&w.w = __floats2half2_rn(acc[6], acc[7]);
    ((uint4*)g_za)[n * 8 + q] = w;
}

// ---------------------------------------------------------------------------
// out = in @ W + b via tf32 mma.sync (m16n8k8), fp32 accumulate, fused stats.
// BN=false: g_za (fp16) -> g_y, stats -> [layer*256 + 0/64)
// BN=true:  in := relu(bn1(g_y)) on load, g_y -> g_z2, stats -> [layer*256+128/192)
// Swizzle: element (row, col) of a 64-wide tile lives at row*64 + (col ^ ((row&7)<<2)).
template <bool BN>
__global__ void __launch_bounds__(128)
gemm_kernel(const float* __restrict__ W, const float* __restrict__ bias,
            const float* __restrict__ gamma, const float* __restrict__ beta,
            int layer) {
    float* out = BN ? g_z2 : g_y;
    __shared__ uint32_t As[128 * 64];  // 32 KB, tf32 bits, swizzled
    __shared__ uint32_t Ws[64 * 64];   // 16 KB, tf32 bits, swizzled
    int t = threadIdx.x;

    // --- W fill (row-major, swizzled, tf32-converted) ---
    #pragma unroll
    for (int p = 0; p < 8; p++) {
        int idx = t + p * 128;
        int k = idx >> 4, kc4 = idx & 15;
        float4 v = __ldg(((const float4*)W) + idx);
        uint4 u = make_uint4(f2tf32(v.x), f2tf32(v.y), f2tf32(v.z), f2tf32(v.w));
        ((uint4*)Ws)[k * 16 + (kc4 ^ (k & 7))] = u;
    }

    // --- BN coefficients (per-thread, registers) ---
    int c4 = t & 15;
    float4 sc, sh;
    if (BN) {
        int c0 = c4 * 4;
        float scv[4], shv[4];
        #pragma unroll
        for (int j = 0; j < 4; j++) {
            float mu  = g_stats[layer * 256 + c0 + j]      * (1.0f / NN);
            float var = g_stats[layer * 256 + 64 + c0 + j] * (1.0f / NN) - mu * mu;
            float s = __ldg(gamma + c0 + j) * rsqrtf(var + 1e-5f);
            scv[j] = s;
            shv[j] = __ldg(beta + c0 + j) - mu * s;
        }
        sc = make_float4(scv[0], scv[1], scv[2], scv[3]);
        sh = make_float4(shv[0], shv[1], shv[2], shv[3]);
    }

    // --- A fill (fp16 load for gemm1, fp32+BN/ReLU for gemm2; swizzled tf32) ---
    const float4* in4 = (const float4*)(g_y + (size_t)blockIdx.x * 128 * DD);
    const uint2*  in2 = ((const uint2*)g_za) + (size_t)blockIdx.x * 128 * 16;
    #pragma unroll
    for (int p = 0; p < 16; p++) {
        int row = (t >> 4) + p * 8;   // row & 7 == t >> 4
        float4 v;
        if (BN) {
            v = __ldg(in4 + row * 16 + c4);
            v.x = fmaxf(fmaf(v.x, sc.x, sh.x), 0.f);
            v.y = fmaxf(fmaf(v.y, sc.y, sh.y), 0.f);
            v.z = fmaxf(fmaf(v.z, sc.z, sh.z), 0.f);
            v.w = fmaxf(fmaf(v.w, sc.w, sh.w), 0.f);
        } else {
            uint2 u = __ldg(in2 + row * 16 + c4);
            float2 f0 = __half22float2(*(__half2*)&u.x);
            float2 f1 = __half22float2(*(__half2*)&u.y);
            v = make_float4(f0.x, f0.y, f1.x, f1.y);
        }
        uint4 u = make_uint4(f2tf32(v.x), f2tf32(v.y), f2tf32(v.z), f2tf32(v.w));
        ((uint4*)As)[row * 16 + (c4 ^ (row & 7))] = u;
    }
    __syncthreads();

    // --- mainloop: 2 m-tiles x 8 n-tiles per warp, 8 k-steps ---
    int lane = t & 31, warp = t >> 5;
    int g = lane >> 2, tig = lane & 3;
    int rbase = warp * 32;
    float c[2][8][4];
    #pragma unroll
    for (int m = 0; m < 2; m++)
        #pragma unroll
        for (int n = 0; n < 8; n++)
            #pragma unroll
            for (int j = 0; j < 4; j++) c[m][n][j] = 0.f;

    int swa = g << 2;  // (row & 7) << 2 for all 4 A rows (g, g+8, +16m)
    #pragma unroll
    for (int k8 = 0; k8 < 64; k8 += 8) {
        uint32_t a[2][4];
        #pragma unroll
        for (int m = 0; m < 2; m++) {
            int r0 = (rbase + m * 16 + g) * 64;
            int r1 = r0 + 8 * 64;
            int cA = (k8 + tig) ^ swa;
            int cB = (k8 + tig + 4) ^ swa;
            a[m][0] = As[r0 + cA];
            a[m][1] = As[r1 + cA];
            a[m][2] = As[r0 + cB];
            a[m][3] = As[r1 + cB];
        }
        #pragma unroll
        for (int n = 0; n < 8; n++) {
            int nc = n * 8 + g;
            uint32_t b0 = Ws[(k8 + tig) * 64 + (nc ^ (tig << 2))];
            uint32_t b1 = Ws[(k8 + tig + 4) * 64 + (nc ^ ((tig + 4) << 2))];
            #pragma unroll
            for (int m = 0; m < 2; m++) {
                asm("mma.sync.aligned.m16n8k8.row.col.f32.tf32.tf32.f32 "
                    "{%0,%1,%2,%3}, {%4,%5,%6,%7}, {%8,%9}, {%0,%1,%2,%3};"
                    : "+f"(c[m][n][0]), "+f"(c[m][n][1]),
                      "+f"(c[m][n][2]), "+f"(c[m][n][3])
                    : "r"(a[m][0]), "r"(a[m][1]), "r"(a[m][2]), "r"(a[m][3]),
                      "r"(b0), "r"(b1));
            }
        }
    }

    // --- epilogue: bias, store, per-column stats ---
    float cs[8][2], cq[8][2];
    #pragma unroll
    for (int n = 0; n < 8; n++) {
        cs[n][0] = cs[n][1] = 0.f;
        cq[n][0] = cq[n][1] = 0.f;
    }
    size_t obase = (size_t)blockIdx.x * 128;
    #pragma unroll
    for (int n = 0; n < 8; n++) {
        int col = n * 8 + 2 * tig;
        float2 bb = __ldg((const float2*)(bias + col));
        #pragma unroll
        for (int m = 0; m < 2; m++) {
            int r0 = rbase + m * 16 + g;
            float2 v0 = make_float2(c[m][n][0] + bb.x, c[m][n][1] + bb.y);
            float2 v1 = make_float2(c[m][n][2] + bb.x, c[m][n][3] + bb.y);
            *(float2*)(out + (obase + r0) * DD + col)     = v0;
            *(float2*)(out + (obase + r0 + 8) * DD + col) = v1;
            cs[n][0] += v0.x + v1.x;      cs[n][1] += v0.y + v1.y;
            cq[n][0] += v0.x * v0.x + v1.x * v1.x;
            cq[n][1] += v0.y * v0.y + v1.y * v1.y;
        }
    }
    // reduce over the 8 g-lane groups (lane stride 4)
    #pragma unroll
    for (int n = 0; n < 8; n++)
        #pragma unroll
        for (int j = 0; j < 2; j++) {
            cs[n][j] += __shfl_xor_sync(0xffffffffu, cs[n][j], 4);
            cs[n][j] += __shfl_xor_sync(0xffffffffu, cs[n][j], 8);
            cs[n][j] += __shfl_xor_sync(0xffffffffu, cs[n][j], 16);
            cq[n][j] += __shfl_xor_sync(0xffffffffu, cq[n][j], 4);
            cq[n][j] += __shfl_xor_sync(0xffffffffu, cq[n][j], 8);
            cq[n][j] += __shfl_xor_sync(0xffffffffu, cq[n][j], 16);
        }
    __syncthreads();           // done reading As/Ws; reuse As as reduction buffer
    float* red = (float*)As;   // [0:256) sums, [256:512) sumsqs
    if (lane < 4) {
        #pragma unroll
        for (int n = 0; n < 8; n++) {
            int col = n * 8 + 2 * lane;
            red[warp * 64 + col]           = cs[n][0];
            red[warp * 64 + col + 1]       = cs[n][1];
            red[256 + warp * 64 + col]     = cq[n][0];
            red[256 + warp * 64 + col + 1] = cq[n][1];
        }
    }
    __syncthreads();
    if (t < 64) {
        float s1 = red[t] + red[64 + t] + red[128 + t] + red[192 + t];
        float s2 = red[256 + t] + red[320 + t] + red[384 + t] + red[448 + t];
        int off = layer * 256 + (BN ? 128 : 0);
        atomicAdd(&g_stats[off + t], s1);
        atomicAdd(&g_stats[off + 64 + t], s2);
    }
}

// ---------------------------------------------------------------------------
// h = relu(bn2(g_z2)); segment-max into out[:, layer*64 : layer*64+64].
// LAST=false: also store h as fp16 into g_xh (next layer's gather source).
template <bool LAST>
__global__ void __launch_bounds__(256)
apply_kernel(const int* __restrict__ n2s, float* __restrict__ out,
             const float* __restrict__ gamma, const float* __restrict__ beta,
             int layer) {
    __shared__ float red[16 * DD];
    __shared__ float ssc[64], ssh[64];
    int t = threadIdx.x, b = blockIdx.x;
    if (t < 64) {
        float mu  = g_stats[layer * 256 + 128 + t] * (1.0f / NN);
        float var = g_stats[layer * 256 + 192 + t] * (1.0f / NN) - mu * mu;
        float s = __ldg(gamma + t) * rsqrtf(var + 1e-5f);
        ssc[t] = s;
        ssh[t] = __ldg(beta + t) - mu * s;
    }
    __syncthreads();

    int g = t >> 4, q = t & 15;
    int c0 = q * 4;
    float s0 = ssc[c0], s1 = ssc[c0 + 1], s2 = ssc[c0 + 2], s3 = ssc[c0 + 3];
    float h0 = ssh[c0], h1 = ssh[c0 + 1], h2 = ssh[c0 + 2], h3 = ssh[c0 + 3];

    float4 m = make_float4(0.f, 0.f, 0.f, 0.f);
    #pragma unroll
    for (int p = 0; p < 4; p++) {
        int row = b * 64 + p * 16 + g;
        float4 v = *(const float4*)(g_z2 + (size_t)row * DD + c0);
        v.x = fmaxf(fmaf(v.x, s0, h0), 0.f);
        v.y = fmaxf(fmaf(v.y, s1, h1), 0.f);
        v.z = fmaxf(fmaf(v.z, s2, h2), 0.f);
        v.w = fmaxf(fmaf(v.w, s3, h3), 0.f);
        if (!LAST) {
            uint2 r;
            *(__half2*)&r.x = __floats2half2_rn(v.x, v.y);
            *(__half2*)&r.y = __floats2half2_rn(v.z, v.w);
            ((uint2*)g_xh)[row * 16 + q] = r;
        }
        m.x = fmaxf(m.x, v.x); m.y = fmaxf(m.y, v.y);
        m.z = fmaxf(m.z, v.z); m.w = fmaxf(m.w, v.w);
    }
    red[g * DD + c0 + 0] = m.x; red[g * DD + c0 + 1] = m.y;
    red[g * DD + c0 + 2] = m.z; red[g * DD + c0 + 3] = m.w;
    __syncthreads();

    if (t < DD) {
        float mv = red[t];
        #pragma unroll
        for (int gg = 1; gg < 16; gg++) mv = fmaxf(mv, red[gg * DD + t]);
        int sA = __ldg(n2s + b * 64), sB = __ldg(n2s + b * 64 + 63);
        if (sA == sB) {
            unsigned* p = (unsigned*)(out + (size_t)sA * 128 + layer * 64 + t);
            asm volatile("red.global.max.u32 [%0], %1;"
                         :: "l"(p), "r"(__float_as_uint(mv)) : "memory");
        } else {
            // correctness fallback: per-row segment max (recompute bn on the fly)
            for (int r = 0; r < 64; r++) {
                int seg = __ldg(n2s + b * 64 + r);
                float zv = g_z2[((size_t)b * 64 + r) * DD + t];
                float v = fmaxf(fmaf(zv, ssc[t], ssh[t]), 0.f);
                unsigned* p = (unsigned*)(out + (size_t)seg * 128 + layer * 64 + t);
                asm volatile("red.global.max.u32 [%0], %1;"
                             :: "l"(p), "r"(__float_as_uint(v)) : "memory");
            }
        }
    }
}

// ---------------------------------------------------------------------------
extern "C" void kernel_launch(void* const* d_in, const int* in_sizes, int n_in,
                              void* d_out, int out_size) {
    const float* x   = (const float*)d_in[0];
    const int*   ei  = (const int*)d_in[1];
    const int*   n2s = (const int*)d_in[2];
    const float* eps = (const float*)d_in[3];
    const float* W1  = (const float*)d_in[4];
    const float* b1  = (const float*)d_in[5];
    const float* gm  = (const float*)d_in[6];
    const float* bm  = (const float*)d_in[7];
    const float* W2  = (const float*)d_in[8];
    const float* b2  = (const float*)d_in[9];
    const float* go  = (const float*)d_in[10];
    const float* bo  = (const float*)d_in[11];
    float* out = (float*)d_out;

    init_kernel<<<NN * DD / 4 / 256, 256>>>(out, x);
    count_slot_kernel<<<EE / 256, 256>>>(ei);
    scan_alloc_kernel<<<NN / 256, 256>>>();
    fill_kernel<<<EE / 256, 256>>>(ei);

    for (int l = 0; l < 2; l++) {
        gather_kernel<<<NN / 32, 256>>>(eps, l);
        gemm_kernel<false><<<NN / 128, 128>>>(W1 + l * DD * DD, b1 + l * DD,
                                              nullptr, nullptr, l);
        gemm_kernel<true><<<NN / 128, 128>>>(W2 + l * DD * DD, b2 + l * DD,
                                             gm + l * DD, bm + l * DD, l);
        if (l == 0)
            apply_kernel<false><<<NN / 64, 256>>>(n2s, out, go, bo, 0);
        else
            apply_kernel<true><<<NN / 64, 256>>>(n2s, out, go + DD, bo + DD, 1);
    }
}